// round 9
// baseline (speedup 1.0000x reference)
#include <cuda_runtime.h>
#include <cuda_bf16.h>
#include <cstdint>

// Problem constants
#define NT 50000
#define NS 100000
#define NE 400000
#define CIN 128
#define CCH 256

// ---------------------------------------------------------------------------
// Scratch (device globals — no allocation allowed)
// ---------------------------------------------------------------------------
__device__ float g_sup0[(size_t)NS * CCH];
__device__ float g_sup1[(size_t)NS * CCH];
__device__ float g_a0[(size_t)NT * CCH];   // fp32 agg OR bf16 pair (aliased)
__device__ float g_b0[(size_t)NT * CCH];   // bf16 activation pair (aliased)
__device__ float g_a1[(size_t)NT * CCH];
__device__ float g_b1[(size_t)NT * CCH];
// bf16 transposed+split weights: [hi | lo] blocks, each [N=256, K] K-major
__device__ __nv_bfloat16 g_wt0[2 * 256 * 128];        // W0^T
__device__ __nv_bfloat16 g_wt1[2 * 256 * 128];        // W1^T
__device__ __nv_bfloat16 g_mwt0[3 * 2 * 256 * 256];   // per-layer [hi|lo]
__device__ __nv_bfloat16 g_mwt1[3 * 2 * 256 * 256];
__device__ __nv_bfloat16 g_wmt[2 * 256 * 512];        // Wm^T (K=512)

// ---------------------------------------------------------------------------
// Helpers
// ---------------------------------------------------------------------------
__device__ __forceinline__ uint32_t smem_u32(const void* p) {
    uint32_t a;
    asm("{ .reg .u64 t; cvta.to.shared.u64 t, %1; cvt.u32.u64 %0, t; }"
        : "=r"(a) : "l"(p));
    return a;
}

__device__ __forceinline__ void ldsm4(uint32_t* r, uint32_t addr) {
    asm volatile("ldmatrix.sync.aligned.m8n8.x4.shared.b16 {%0,%1,%2,%3}, [%4];"
                 : "=r"(r[0]), "=r"(r[1]), "=r"(r[2]), "=r"(r[3]) : "r"(addr));
}

__device__ __forceinline__ void mma16816(float* d, const uint32_t* a, const uint32_t* b) {
    asm volatile(
        "mma.sync.aligned.m16n8k16.row.col.f32.bf16.bf16.f32 "
        "{%0,%1,%2,%3}, {%4,%5,%6,%7}, {%8,%9}, {%0,%1,%2,%3};"
        : "+f"(d[0]), "+f"(d[1]), "+f"(d[2]), "+f"(d[3])
        : "r"(a[0]), "r"(a[1]), "r"(a[2]), "r"(a[3]), "r"(b[0]), "r"(b[1]));
}

__device__ __forceinline__ uint32_t pack2(__nv_bfloat16 x, __nv_bfloat16 y) {
    return ((uint32_t)__bfloat16_as_ushort(y) << 16) | __bfloat16_as_ushort(x);
}

// ---------------------------------------------------------------------------
// Weight prep: W [K, 256] fp32 -> Wt_hi/Wt_lo [256, K] bf16 (K-major)
// Batched over grid.y layers
// ---------------------------------------------------------------------------
__global__ __launch_bounds__(256) void prep_w(
    const float* __restrict__ W, __nv_bfloat16* __restrict__ hi,
    __nv_bfloat16* __restrict__ lo, int K)
{
    int l = blockIdx.y;
    const float* Wl = W + (size_t)l * K * 256;
    __nv_bfloat16* hil = hi + (size_t)l * 2 * K * 256;
    __nv_bfloat16* lol = lo + (size_t)l * 2 * K * 256;
    int idx = blockIdx.x * 256 + threadIdx.x;
    if (idx >= K * 256) return;
    int k = idx >> 8;
    int n = idx & 255;
    float x = Wl[idx];
    __nv_bfloat16 h = __float2bfloat16(x);
    float r = x - __bfloat162float(h);
    hil[(size_t)n * K + k] = h;
    lol[(size_t)n * K + k] = __float2bfloat16(r);
}

// ---------------------------------------------------------------------------
// Split-bf16 mma.sync GEMM, dual-branch via blockIdx.z.
// A16: A pre-split bf16 hi/lo [M,256]; else fp32 A split on the fly.
// A2hi/A2lo: second A source for k >= 256 (merge, Ktot=512).
// OUT16: epilogue emits split bf16 hi/lo; else fp32.
// Block: 256 thr, tile 128x128, BK=32, double-buffered smem, occ 2.
// ---------------------------------------------------------------------------
#define ROWB 80
#define BUF  (128 * ROWB)
#define STAGE (4 * BUF)
#define SMEMT (2 * STAGE)

struct GP {
    const float* A32[2];
    const __nv_bfloat16 *Ahi[2], *Alo[2];
    const __nv_bfloat16 *A2hi, *A2lo;
    const __nv_bfloat16 *Bhi[2], *Blo[2];
    const float* bias[2];
    float* C32[2];
    __nv_bfloat16 *Chi[2], *Clo[2];
    int M, Ktot, lda;
};

template <bool A16, bool OUT16, bool BIAS, bool RELU>
__global__ __launch_bounds__(256, 2) void mma_gemm(GP p)
{
    extern __shared__ char smem[];
    const uint32_t sb = smem_u32(smem);
    const int tid = threadIdx.x;
    const int wid = tid >> 5;
    const int lane = tid & 31;
    const int warpM = wid >> 2;
    const int warpN = wid & 3;
    const int bm = blockIdx.x * 128;
    const int bn = blockIdx.y * 128;
    const int z = blockIdx.z;
    const int M = p.M, Ktot = p.Ktot, lda = p.lda;

    float acc[4][4][4];
#pragma unroll
    for (int i = 0; i < 4; i++)
#pragma unroll
        for (int j = 0; j < 4; j++)
#pragma unroll
            for (int q = 0; q < 4; q++) acc[i][j][q] = 0.0f;

    float4 aReg[4];              // A32 staging
    uint4 ahReg[2], alReg[2];    // A16 staging
    uint4 bhReg[2], blReg[2];

    auto loadG = [&](int c) {
        const int k0 = c << 5;
        if (A16) {
            const __nv_bfloat16* Ah = p.Ahi[z];
            const __nv_bfloat16* Al = p.Alo[z];
            int kk = k0;
            if (p.A2hi != nullptr && k0 >= 256) { Ah = p.A2hi; Al = p.A2lo; kk = k0 - 256; }
#pragma unroll
            for (int i = 0; i < 2; i++) {
                int idx = i * 256 + tid;
                int r = idx >> 2, ch = idx & 3;
                int row = bm + r;
                if (row < M) {
                    size_t g = (size_t)row * lda + kk + ch * 8;
                    ahReg[i] = __ldg((const uint4*)(Ah + g));
                    alReg[i] = __ldg((const uint4*)(Al + g));
                } else {
                    ahReg[i] = make_uint4(0, 0, 0, 0);
                    alReg[i] = make_uint4(0, 0, 0, 0);
                }
            }
        } else {
            const float* Ap = p.A32[z];
#pragma unroll
            for (int i = 0; i < 4; i++) {
                int idx = i * 256 + tid;
                int r = idx >> 3, c4 = idx & 7;
                int row = bm + r;
                aReg[i] = (row < M)
                    ? __ldg((const float4*)(Ap + (size_t)row * lda + k0) + c4)
                    : make_float4(0.f, 0.f, 0.f, 0.f);
            }
        }
        const __nv_bfloat16* Bh = p.Bhi[z];
        const __nv_bfloat16* Bl = p.Blo[z];
#pragma unroll
        for (int i = 0; i < 2; i++) {
            int idx = i * 256 + tid;
            int r = idx >> 2, ch = idx & 3;
            size_t g = (size_t)(bn + r) * Ktot + k0 + ch * 8;
            bhReg[i] = __ldg((const uint4*)(Bh + g));
            blReg[i] = __ldg((const uint4*)(Bl + g));
        }
    };

    auto storeS = [&](int s) {
        char* st = smem + s * STAGE;
        if (A16) {
#pragma unroll
            for (int i = 0; i < 2; i++) {
                int idx = i * 256 + tid;
                int r = idx >> 2, ch = idx & 3;
                uint32_t off = (uint32_t)(r * ROWB + ch * 16);
                *(uint4*)(st + off) = ahReg[i];
                *(uint4*)(st + BUF + off) = alReg[i];
            }
        } else {
#pragma unroll
            for (int i = 0; i < 4; i++) {
                int idx = i * 256 + tid;
                int r = idx >> 3, c4 = idx & 7;
                uint32_t off = (uint32_t)(r * ROWB + c4 * 8);
                float4 v = aReg[i];
                __nv_bfloat16 h0 = __float2bfloat16(v.x);
                __nv_bfloat16 h1 = __float2bfloat16(v.y);
                __nv_bfloat16 h2 = __float2bfloat16(v.z);
                __nv_bfloat16 h3 = __float2bfloat16(v.w);
                uint2 ph, pl;
                ph.x = pack2(h0, h1);
                ph.y = pack2(h2, h3);
                pl.x = pack2(__float2bfloat16(v.x - __bfloat162float(h0)),
                             __float2bfloat16(v.y - __bfloat162float(h1)));
                pl.y = pack2(__float2bfloat16(v.z - __bfloat162float(h2)),
                             __float2bfloat16(v.w - __bfloat162float(h3)));
                *(uint2*)(st + off) = ph;
                *(uint2*)(st + BUF + off) = pl;
            }
        }
#pragma unroll
        for (int i = 0; i < 2; i++) {
            int idx = i * 256 + tid;
            int r = idx >> 2, ch = idx & 3;
            uint32_t off = (uint32_t)(r * ROWB + ch * 16);
            *(uint4*)(st + 2 * BUF + off) = bhReg[i];
            *(uint4*)(st + 3 * BUF + off) = blReg[i];
        }
    };

    auto mmaS = [&](int s) {
        const uint32_t base = sb + s * STAGE;
#pragma unroll
        for (int ks = 0; ks < 2; ks++) {
            uint32_t bhf[4][2], blf[4][2];
#pragma unroll
            for (int ntp = 0; ntp < 2; ntp++) {
                int rB = warpN * 32 + ntp * 16 + ((lane >> 4) & 1) * 8 + (lane & 7);
                int cB = ks * 2 + ((lane >> 3) & 1);
                uint32_t addr = base + 2 * BUF + rB * ROWB + cB * 16;
                uint32_t q[4];
                ldsm4(q, addr);
                bhf[ntp * 2][0] = q[0]; bhf[ntp * 2][1] = q[1];
                bhf[ntp * 2 + 1][0] = q[2]; bhf[ntp * 2 + 1][1] = q[3];
                ldsm4(q, addr + BUF);
                blf[ntp * 2][0] = q[0]; blf[ntp * 2][1] = q[1];
                blf[ntp * 2 + 1][0] = q[2]; blf[ntp * 2 + 1][1] = q[3];
            }
#pragma unroll
            for (int mt = 0; mt < 4; mt++) {
                int rA = warpM * 64 + mt * 16 + (lane & 15);
                int cA = ks * 2 + (lane >> 4);
                uint32_t addr = base + rA * ROWB + cA * 16;
                uint32_t ah[4], al[4];
                ldsm4(ah, addr);
                ldsm4(al, addr + BUF);
#pragma unroll
                for (int nt = 0; nt < 4; nt++) {
                    mma16816(acc[mt][nt], ah, bhf[nt]);
                    mma16816(acc[mt][nt], ah, blf[nt]);
                    mma16816(acc[mt][nt], al, bhf[nt]);
                }
            }
        }
    };

    const int nch = Ktot >> 5;
    loadG(0);
    storeS(0);
    __syncthreads();
    for (int c = 0; c < nch; c++) {
        if (c + 1 < nch) loadG(c + 1);
        mmaS(c & 1);
        if (c + 1 < nch) storeS((c + 1) & 1);
        __syncthreads();
    }

    // Epilogue
    const float* bias = BIAS ? p.bias[z] : nullptr;
#pragma unroll
    for (int mt = 0; mt < 4; mt++) {
        int row0 = bm + warpM * 64 + mt * 16 + (lane >> 2);
#pragma unroll
        for (int nt = 0; nt < 4; nt++) {
            int col = bn + warpN * 32 + nt * 8 + (lane & 3) * 2;
            float bx = 0.f, by = 0.f;
            if (BIAS) { bx = __ldg(bias + col); by = __ldg(bias + col + 1); }
            float2 v0 = make_float2(acc[mt][nt][0] + bx, acc[mt][nt][1] + by);
            float2 v1 = make_float2(acc[mt][nt][2] + bx, acc[mt][nt][3] + by);
            if (RELU) {
                v0.x = fmaxf(v0.x, 0.f); v0.y = fmaxf(v0.y, 0.f);
                v1.x = fmaxf(v1.x, 0.f); v1.y = fmaxf(v1.y, 0.f);
            }
            if (OUT16) {
                __nv_bfloat16* Chi = p.Chi[z];
                __nv_bfloat16* Clo = p.Clo[z];
#pragma unroll
                for (int h = 0; h < 2; h++) {
                    int row = row0 + h * 8;
                    if (row >= M) continue;
                    float ex = h ? v1.x : v0.x;
                    float ey = h ? v1.y : v0.y;
                    __nv_bfloat16 hx = __float2bfloat16(ex);
                    __nv_bfloat16 hy = __float2bfloat16(ey);
                    size_t o = (size_t)row * 256 + col;
                    *(uint32_t*)(Chi + o) = pack2(hx, hy);
                    *(uint32_t*)(Clo + o) =
                        pack2(__float2bfloat16(ex - __bfloat162float(hx)),
                              __float2bfloat16(ey - __bfloat162float(hy)));
                }
            } else {
                float* C = p.C32[z];
                if (row0 < M)     *(float2*)(C + (size_t)row0 * 256 + col) = v0;
                if (row0 + 8 < M) *(float2*)(C + (size_t)(row0 + 8) * 256 + col) = v1;
            }
        }
    }
}

// ---------------------------------------------------------------------------
// Edge scatter: agg[rows[e]] += vals[e] * support[cols[e]]  (256 channels)
// 64 threads/edge, one red.global.add.v4.f32 per 16B.
// ---------------------------------------------------------------------------
__global__ __launch_bounds__(256) void scatter_kernel(
    const float* __restrict__ sup, const float* __restrict__ vals,
    const int* __restrict__ rows, const int* __restrict__ cols,
    float* __restrict__ agg)
{
    long long idx = (long long)blockIdx.x * blockDim.x + threadIdx.x;
    if (idx >= (long long)NE * 64) return;
    int e = (int)(idx >> 6);
    int q = (int)(idx & 63);
    int r = __ldg(rows + e);
    int c = __ldg(cols + e);
    float v = __ldg(vals + e);
    float4 s = __ldg((const float4*)(sup + (size_t)c * CCH) + q);
    float* dst = agg + (size_t)r * CCH + q * 4;
    asm volatile("red.global.add.v4.f32 [%0], {%1, %2, %3, %4};"
                 :: "l"(dst), "f"(v * s.x), "f"(v * s.y),
                    "f"(v * s.z), "f"(v * s.w)
                 : "memory");
}

// ---------------------------------------------------------------------------
extern "C" void kernel_launch(void* const* d_in, const int* in_sizes, int n_in,
                              void* d_out, int out_size)
{
    const float* x_t  = (const float*)d_in[0];
    const float* xs0  = (const float*)d_in[1];
    const float* xs1  = (const float*)d_in[2];
    const float* v0   = (const float*)d_in[3];
    const float* v1   = (const float*)d_in[4];
    const int*   r0   = (const int*)d_in[5];
    const int*   c0   = (const int*)d_in[6];
    const int*   r1   = (const int*)d_in[7];
    const int*   c1   = (const int*)d_in[8];
    const float* W0   = (const float*)d_in[9];
    const float* W1   = (const float*)d_in[10];
    const float* mW0  = (const float*)d_in[11];
    const float* mb0  = (const float*)d_in[12];
    const float* mW1  = (const float*)d_in[13];
    const float* mb1  = (const float*)d_in[14];
    const float* Wm   = (const float*)d_in[15];
    const float* bmv  = (const float*)d_in[16];
    float* out = (float*)d_out;

    float *sup0, *sup1, *a0, *b0, *a1, *b1;
    __nv_bfloat16 *wt0, *wt1, *mwt0, *mwt1, *wmt;
    cudaGetSymbolAddress((void**)&sup0, g_sup0);
    cudaGetSymbolAddress((void**)&sup1, g_sup1);
    cudaGetSymbolAddress((void**)&a0, g_a0);
    cudaGetSymbolAddress((void**)&b0, g_b0);
    cudaGetSymbolAddress((void**)&a1, g_a1);
    cudaGetSymbolAddress((void**)&b1, g_b1);
    cudaGetSymbolAddress((void**)&wt0, g_wt0);
    cudaGetSymbolAddress((void**)&wt1, g_wt1);
    cudaGetSymbolAddress((void**)&mwt0, g_mwt0);
    cudaGetSymbolAddress((void**)&mwt1, g_mwt1);
    cudaGetSymbolAddress((void**)&wmt, g_wmt);

    // bf16 activation pairs aliased into fp32 scratch (same byte count)
    const size_t NTC = (size_t)NT * CCH;
    __nv_bfloat16* h0h = (__nv_bfloat16*)b0;  __nv_bfloat16* h0l = h0h + NTC;
    __nv_bfloat16* h1h = (__nv_bfloat16*)b1;  __nv_bfloat16* h1l = h1h + NTC;
    __nv_bfloat16* q0h = (__nv_bfloat16*)a0;  __nv_bfloat16* q0l = q0h + NTC;
    __nv_bfloat16* q1h = (__nv_bfloat16*)a1;  __nv_bfloat16* q1l = q1h + NTC;

    cudaFuncSetAttribute(mma_gemm<false, false, false, false>,
                         cudaFuncAttributeMaxDynamicSharedMemorySize, SMEMT);
    cudaFuncSetAttribute(mma_gemm<false, true, true, true>,
                         cudaFuncAttributeMaxDynamicSharedMemorySize, SMEMT);
    cudaFuncSetAttribute(mma_gemm<true, true, true, true>,
                         cudaFuncAttributeMaxDynamicSharedMemorySize, SMEMT);
    cudaFuncSetAttribute(mma_gemm<true, false, true, false>,
                         cudaFuncAttributeMaxDynamicSharedMemorySize, SMEMT);

    // ---- Weight prep ----
    dim3 gp1((128 * 256 + 255) / 256, 1);
    prep_w<<<gp1, 256>>>(W0, wt0, wt0 + 256 * 128, 128);
    prep_w<<<gp1, 256>>>(W1, wt1, wt1 + 256 * 128, 128);
    dim3 gp3((256 * 256 + 255) / 256, 3);
    prep_w<<<gp3, 256>>>(mW0, mwt0, mwt0 + 65536, 256);
    prep_w<<<gp3, 256>>>(mW1, mwt1, mwt1 + 65536, 256);
    dim3 gpm((512 * 256 + 255) / 256, 1);
    prep_w<<<gpm, 256>>>(Wm, wmt, wmt + 256 * 512, 512);

    dim3 blk(256);
    dim3 gS((NS + 127) / 128, 2, 2);
    dim3 gT2((NT + 127) / 128, 2, 2);
    dim3 gT1((NT + 127) / 128, 2, 1);

    GP p{};

    // support = x_src @ W   (both branches, one launch)
    p = GP{};
    p.A32[0] = xs0; p.A32[1] = xs1;
    p.Bhi[0] = wt0; p.Blo[0] = wt0 + 256 * 128;
    p.Bhi[1] = wt1; p.Blo[1] = wt1 + 256 * 128;
    p.C32[0] = sup0; p.C32[1] = sup1;
    p.M = NS; p.Ktot = 128; p.lda = 128;
    mma_gemm<false, false, false, false><<<gS, blk, SMEMT>>>(p);

    // agg init = x_target (epsilon = 0)
    cudaMemcpyAsync(a0, x_t, sizeof(float) * NTC, cudaMemcpyDeviceToDevice);
    cudaMemcpyAsync(a1, x_t, sizeof(float) * NTC, cudaMemcpyDeviceToDevice);

    // sparse scatter-add
    int sblocks = (int)(((long long)NE * 64 + 255) / 256);
    scatter_kernel<<<sblocks, blk>>>(sup0, v0, r0, c0, a0);
    scatter_kernel<<<sblocks, blk>>>(sup1, v1, r1, c1, a1);

    // MLP layer 1: fp32 agg -> split bf16 h  (both branches)
    p = GP{};
    p.A32[0] = a0; p.A32[1] = a1;
    p.Bhi[0] = mwt0; p.Blo[0] = mwt0 + 65536;
    p.Bhi[1] = mwt1; p.Blo[1] = mwt1 + 65536;
    p.bias[0] = mb0; p.bias[1] = mb1;
    p.Chi[0] = h0h; p.Clo[0] = h0l;
    p.Chi[1] = h1h; p.Clo[1] = h1l;
    p.M = NT; p.Ktot = 256; p.lda = 256;
    mma_gemm<false, true, true, true><<<gT2, blk, SMEMT>>>(p);

    // MLP layer 2: split bf16 h -> split bf16 q   (a0/a1 fp32 now dead)
    p = GP{};
    p.Ahi[0] = h0h; p.Alo[0] = h0l;
    p.Ahi[1] = h1h; p.Alo[1] = h1l;
    p.Bhi[0] = mwt0 + 2 * 65536; p.Blo[0] = mwt0 + 3 * 65536;
    p.Bhi[1] = mwt1 + 2 * 65536; p.Blo[1] = mwt1 + 3 * 65536;
    p.bias[0] = mb0 + 256; p.bias[1] = mb1 + 256;
    p.Chi[0] = q0h; p.Clo[0] = q0l;
    p.Chi[1] = q1h; p.Clo[1] = q1l;
    p.M = NT; p.Ktot = 256; p.lda = 256;
    mma_gemm<true, true, true, true><<<gT2, blk, SMEMT>>>(p);

    // MLP layer 3: q -> h
    p = GP{};
    p.Ahi[0] = q0h; p.Alo[0] = q0l;
    p.Ahi[1] = q1h; p.Alo[1] = q1l;
    p.Bhi[0] = mwt0 + 4 * 65536; p.Blo[0] = mwt0 + 5 * 65536;
    p.Bhi[1] = mwt1 + 4 * 65536; p.Blo[1] = mwt1 + 5 * 65536;
    p.bias[0] = mb0 + 512; p.bias[1] = mb1 + 512;
    p.Chi[0] = h0h; p.Clo[0] = h0l;
    p.Chi[1] = h1h; p.Clo[1] = h1l;
    p.M = NT; p.Ktot = 256; p.lda = 256;
    mma_gemm<true, true, true, true><<<gT2, blk, SMEMT>>>(p);

    // merge: out = [h0, h1] @ Wm + bm  (K=512, dual bf16 A sources)
    p = GP{};
    p.Ahi[0] = h0h; p.Alo[0] = h0l;
    p.A2hi = h1h;  p.A2lo = h1l;
    p.Bhi[0] = wmt; p.Blo[0] = wmt + 256 * 512;
    p.bias[0] = bmv;
    p.C32[0] = out;
    p.M = NT; p.Ktot = 512; p.lda = 256;
    mma_gemm<true, false, true, false><<<gT1, blk, SMEMT>>>(p);
}

// round 10
// speedup vs baseline: 1.3600x; 1.3600x over previous
#include <cuda_runtime.h>
#include <cuda_fp16.h>
#include <cstdint>

// Problem constants
#define NT 50000
#define NS 100000
#define NE 400000
#define CIN 128
#define CCH 256

// ---------------------------------------------------------------------------
// Scratch (device globals — no allocation allowed)
// ---------------------------------------------------------------------------
__device__ float g_sup0[(size_t)NS * CCH];
__device__ float g_sup1[(size_t)NS * CCH];
__device__ float g_a0[(size_t)NT * CCH];
__device__ float g_b0[(size_t)NT * CCH];
__device__ float g_a1[(size_t)NT * CCH];
__device__ float g_b1[(size_t)NT * CCH];
// fp16 transposed weights: [N=256, K] K-major (single rounding; A carries the split)
__device__ __half g_wt0[256 * 128];        // W0^T
__device__ __half g_wt1[256 * 128];        // W1^T
__device__ __half g_mwt0[3 * 256 * 256];   // per-layer
__device__ __half g_mwt1[3 * 256 * 256];
__device__ __half g_wmt[256 * 512];        // Wm^T (K=512)

// ---------------------------------------------------------------------------
// Helpers
// ---------------------------------------------------------------------------
__device__ __forceinline__ uint32_t smem_u32(const void* p) {
    uint32_t a;
    asm("{ .reg .u64 t; cvta.to.shared.u64 t, %1; cvt.u32.u64 %0, t; }"
        : "=r"(a) : "l"(p));
    return a;
}

__device__ __forceinline__ void ldsm4(uint32_t* r, uint32_t addr) {
    asm volatile("ldmatrix.sync.aligned.m8n8.x4.shared.b16 {%0,%1,%2,%3}, [%4];"
                 : "=r"(r[0]), "=r"(r[1]), "=r"(r[2]), "=r"(r[3]) : "r"(addr));
}

__device__ __forceinline__ void mma16816(float* d, const uint32_t* a, const uint32_t* b) {
    asm volatile(
        "mma.sync.aligned.m16n8k16.row.col.f32.f16.f16.f32 "
        "{%0,%1,%2,%3}, {%4,%5,%6,%7}, {%8,%9}, {%0,%1,%2,%3};"
        : "+f"(d[0]), "+f"(d[1]), "+f"(d[2]), "+f"(d[3])
        : "r"(a[0]), "r"(a[1]), "r"(a[2]), "r"(a[3]), "r"(b[0]), "r"(b[1]));
}

__device__ __forceinline__ uint32_t pack2h(__half x, __half y) {
    return ((uint32_t)__half_as_ushort(y) << 16) | __half_as_ushort(x);
}

// ---------------------------------------------------------------------------
// Weight prep: W [K, 256] fp32 -> Wt [256, K] fp16 (K-major, single rounding)
// Batched over grid.y layers
// ---------------------------------------------------------------------------
__global__ __launch_bounds__(256) void prep_w(
    const float* __restrict__ W, __half* __restrict__ Wt, int K)
{
    int l = blockIdx.y;
    const float* Wl = W + (size_t)l * K * 256;
    __half* Wtl = Wt + (size_t)l * K * 256;
    int idx = blockIdx.x * 256 + threadIdx.x;
    if (idx >= K * 256) return;
    int k = idx >> 8;
    int n = idx & 255;
    Wtl[(size_t)n * K + k] = __float2half(Wl[idx]);
}

// ---------------------------------------------------------------------------
// Split-fp16 mma.sync GEMM:  C[M,256] = relu?( A[M,Ktot] @ Bt^T + bias )
// A fp32, split on the fly into exact fp16 hi/lo (2 MMAs per product:
// ah*b + al*b; B rounding is the only error source, ~2^-12 relative).
// Bt pre-rounded fp16 [256, Ktot] K-major.
// A2: optional second fp32 A source for k >= 256 (merge GEMM, Ktot=512).
// Block: 256 thr (8 warps), tile 128x128, BK=32, double-buffered smem.
// Warp (warpM 0-1, warpN 0-3): 64x32 out = 4x4 m16n8k16 tiles, 2 MMAs each.
// Smem row stride 80B (64B data + 16B pad) -> conflict-free ldmatrix.
// ---------------------------------------------------------------------------
#define ROWB 80
#define BUF  (128 * ROWB)          /* 10240 B per operand buffer  */
#define STAGE (3 * BUF)            /* AH, AL, B = 30720 B          */
#define SMEMT (2 * STAGE)          /* 61440 B                      */

template <bool BIAS, bool RELU>
__global__ __launch_bounds__(256, 2) void mma_gemm(
    const float* __restrict__ A, const float* __restrict__ A2,
    const __half* __restrict__ Bt,
    const float* __restrict__ bias, float* __restrict__ C,
    int M, int Ktot, int lda)
{
    extern __shared__ char smem[];
    const uint32_t sb = smem_u32(smem);
    const int tid = threadIdx.x;
    const int wid = tid >> 5;
    const int lane = tid & 31;
    const int warpM = wid >> 2;   // 0-1 -> 64 rows each
    const int warpN = wid & 3;    // 0-3 -> 32 cols each
    const int bm = blockIdx.x * 128;
    const int bn = blockIdx.y * 128;

    float acc[4][4][4];
#pragma unroll
    for (int i = 0; i < 4; i++)
#pragma unroll
        for (int j = 0; j < 4; j++)
#pragma unroll
            for (int q = 0; q < 4; q++) acc[i][j][q] = 0.0f;

    float4 aReg[4];
    uint4 bReg[2];

    auto loadG = [&](int c) {
        const int k0 = c << 5;
        const float* Ap = A;
        int kk = k0;
        if (A2 != nullptr && k0 >= 256) { Ap = A2; kk = k0 - 256; }
#pragma unroll
        for (int i = 0; i < 4; i++) {
            int idx = i * 256 + tid;
            int r = idx >> 3, c4 = idx & 7;
            int row = bm + r;
            aReg[i] = (row < M)
                ? __ldg((const float4*)(Ap + (size_t)row * lda + kk) + c4)
                : make_float4(0.f, 0.f, 0.f, 0.f);
        }
#pragma unroll
        for (int i = 0; i < 2; i++) {
            int idx = i * 256 + tid;
            int r = idx >> 2, ch = idx & 3;
            size_t g = (size_t)(bn + r) * Ktot + k0 + ch * 8;
            bReg[i] = __ldg((const uint4*)(Bt + g));
        }
    };

    auto storeS = [&](int s) {
        char* st = smem + s * STAGE;
#pragma unroll
        for (int i = 0; i < 4; i++) {
            int idx = i * 256 + tid;
            int r = idx >> 3, c4 = idx & 7;
            uint32_t off = (uint32_t)(r * ROWB + c4 * 8);
            float4 v = aReg[i];
            __half h0 = __float2half(v.x);
            __half h1 = __float2half(v.y);
            __half h2 = __float2half(v.z);
            __half h3 = __float2half(v.w);
            uint2 ph, pl;
            ph.x = pack2h(h0, h1);
            ph.y = pack2h(h2, h3);
            pl.x = pack2h(__float2half(v.x - __half2float(h0)),
                          __float2half(v.y - __half2float(h1)));
            pl.y = pack2h(__float2half(v.z - __half2float(h2)),
                          __float2half(v.w - __half2float(h3)));
            *(uint2*)(st + off) = ph;
            *(uint2*)(st + BUF + off) = pl;
        }
#pragma unroll
        for (int i = 0; i < 2; i++) {
            int idx = i * 256 + tid;
            int r = idx >> 2, ch = idx & 3;
            uint32_t off = (uint32_t)(r * ROWB + ch * 16);
            *(uint4*)(st + 2 * BUF + off) = bReg[i];
        }
    };

    auto mmaS = [&](int s) {
        const uint32_t base = sb + s * STAGE;
#pragma unroll
        for (int ks = 0; ks < 2; ks++) {
            uint32_t bf[4][2];
#pragma unroll
            for (int ntp = 0; ntp < 2; ntp++) {
                int rB = warpN * 32 + ntp * 16 + ((lane >> 4) & 1) * 8 + (lane & 7);
                int cB = ks * 2 + ((lane >> 3) & 1);
                uint32_t addr = base + 2 * BUF + rB * ROWB + cB * 16;
                uint32_t q[4];
                ldsm4(q, addr);
                bf[ntp * 2][0] = q[0]; bf[ntp * 2][1] = q[1];
                bf[ntp * 2 + 1][0] = q[2]; bf[ntp * 2 + 1][1] = q[3];
            }
#pragma unroll
            for (int mt = 0; mt < 4; mt++) {
                int rA = warpM * 64 + mt * 16 + (lane & 15);
                int cA = ks * 2 + (lane >> 4);
                uint32_t addr = base + rA * ROWB + cA * 16;
                uint32_t ah[4], al[4];
                ldsm4(ah, addr);
                ldsm4(al, addr + BUF);
#pragma unroll
                for (int nt = 0; nt < 4; nt++) {
                    mma16816(acc[mt][nt], ah, bf[nt]);
                    mma16816(acc[mt][nt], al, bf[nt]);
                }
            }
        }
    };

    const int nch = Ktot >> 5;
    loadG(0);
    storeS(0);
    __syncthreads();
    for (int c = 0; c < nch; c++) {
        if (c + 1 < nch) loadG(c + 1);
        mmaS(c & 1);
        if (c + 1 < nch) storeS((c + 1) & 1);
        __syncthreads();
    }

    // Epilogue
#pragma unroll
    for (int mt = 0; mt < 4; mt++) {
        int row0 = bm + warpM * 64 + mt * 16 + (lane >> 2);
#pragma unroll
        for (int nt = 0; nt < 4; nt++) {
            int col = bn + warpN * 32 + nt * 8 + (lane & 3) * 2;
            float bx = 0.f, by = 0.f;
            if (BIAS) { bx = __ldg(bias + col); by = __ldg(bias + col + 1); }
            float2 v0 = make_float2(acc[mt][nt][0] + bx, acc[mt][nt][1] + by);
            float2 v1 = make_float2(acc[mt][nt][2] + bx, acc[mt][nt][3] + by);
            if (RELU) {
                v0.x = fmaxf(v0.x, 0.f); v0.y = fmaxf(v0.y, 0.f);
                v1.x = fmaxf(v1.x, 0.f); v1.y = fmaxf(v1.y, 0.f);
            }
            if (row0 < M)     *(float2*)(C + (size_t)row0 * 256 + col) = v0;
            if (row0 + 8 < M) *(float2*)(C + (size_t)(row0 + 8) * 256 + col) = v1;
        }
    }
}

// ---------------------------------------------------------------------------
// Edge scatter: agg[rows[e]] += vals[e] * support[cols[e]]  (256 channels)
// 64 threads/edge, one red.global.add.v4.f32 per 16B.
// ---------------------------------------------------------------------------
__global__ __launch_bounds__(256) void scatter_kernel(
    const float* __restrict__ sup, const float* __restrict__ vals,
    const int* __restrict__ rows, const int* __restrict__ cols,
    float* __restrict__ agg)
{
    long long idx = (long long)blockIdx.x * blockDim.x + threadIdx.x;
    if (idx >= (long long)NE * 64) return;
    int e = (int)(idx >> 6);
    int q = (int)(idx & 63);
    int r = __ldg(rows + e);
    int c = __ldg(cols + e);
    float v = __ldg(vals + e);
    float4 s = __ldg((const float4*)(sup + (size_t)c * CCH) + q);
    float* dst = agg + (size_t)r * CCH + q * 4;
    asm volatile("red.global.add.v4.f32 [%0], {%1, %2, %3, %4};"
                 :: "l"(dst), "f"(v * s.x), "f"(v * s.y),
                    "f"(v * s.z), "f"(v * s.w)
                 : "memory");
}

// ---------------------------------------------------------------------------
extern "C" void kernel_launch(void* const* d_in, const int* in_sizes, int n_in,
                              void* d_out, int out_size)
{
    const float* x_t  = (const float*)d_in[0];
    const float* xs0  = (const float*)d_in[1];
    const float* xs1  = (const float*)d_in[2];
    const float* v0   = (const float*)d_in[3];
    const float* v1   = (const float*)d_in[4];
    const int*   r0   = (const int*)d_in[5];
    const int*   c0   = (const int*)d_in[6];
    const int*   r1   = (const int*)d_in[7];
    const int*   c1   = (const int*)d_in[8];
    const float* W0   = (const float*)d_in[9];
    const float* W1   = (const float*)d_in[10];
    const float* mW0  = (const float*)d_in[11];
    const float* mb0  = (const float*)d_in[12];
    const float* mW1  = (const float*)d_in[13];
    const float* mb1  = (const float*)d_in[14];
    const float* Wm   = (const float*)d_in[15];
    const float* bmv  = (const float*)d_in[16];
    float* out = (float*)d_out;

    float *sup0, *sup1, *a0, *b0, *a1, *b1;
    __half *wt0, *wt1, *mwt0, *mwt1, *wmt;
    cudaGetSymbolAddress((void**)&sup0, g_sup0);
    cudaGetSymbolAddress((void**)&sup1, g_sup1);
    cudaGetSymbolAddress((void**)&a0, g_a0);
    cudaGetSymbolAddress((void**)&b0, g_b0);
    cudaGetSymbolAddress((void**)&a1, g_a1);
    cudaGetSymbolAddress((void**)&b1, g_b1);
    cudaGetSymbolAddress((void**)&wt0, g_wt0);
    cudaGetSymbolAddress((void**)&wt1, g_wt1);
    cudaGetSymbolAddress((void**)&mwt0, g_mwt0);
    cudaGetSymbolAddress((void**)&mwt1, g_mwt1);
    cudaGetSymbolAddress((void**)&wmt, g_wmt);

    cudaFuncSetAttribute(mma_gemm<false, false>,
                         cudaFuncAttributeMaxDynamicSharedMemorySize, SMEMT);
    cudaFuncSetAttribute(mma_gemm<true, true>,
                         cudaFuncAttributeMaxDynamicSharedMemorySize, SMEMT);
    cudaFuncSetAttribute(mma_gemm<true, false>,
                         cudaFuncAttributeMaxDynamicSharedMemorySize, SMEMT);

    // ---- Weight prep: transpose + fp16 round (batched) ----
    dim3 gp1((128 * 256 + 255) / 256, 1);
    prep_w<<<gp1, 256>>>(W0, wt0, 128);
    prep_w<<<gp1, 256>>>(W1, wt1, 128);
    dim3 gp3((256 * 256 + 255) / 256, 3);
    prep_w<<<gp3, 256>>>(mW0, mwt0, 256);
    prep_w<<<gp3, 256>>>(mW1, mwt1, 256);
    dim3 gpm((512 * 256 + 255) / 256, 1);
    prep_w<<<gpm, 256>>>(Wm, wmt, 512);

    dim3 blk(256);
    dim3 gS((NS + 127) / 128, 2);   // support GEMMs: 782 x 2
    dim3 gT((NT + 127) / 128, 2);   // target GEMMs:  391 x 2

    // support = x_src @ W
    mma_gemm<false, false><<<gS, blk, SMEMT>>>(
        xs0, nullptr, wt0, nullptr, sup0, NS, 128, 128);
    mma_gemm<false, false><<<gS, blk, SMEMT>>>(
        xs1, nullptr, wt1, nullptr, sup1, NS, 128, 128);

    // agg init = x_target (epsilon = 0)
    cudaMemcpyAsync(a0, x_t, sizeof(float) * (size_t)NT * CCH, cudaMemcpyDeviceToDevice);
    cudaMemcpyAsync(a1, x_t, sizeof(float) * (size_t)NT * CCH, cudaMemcpyDeviceToDevice);

    // sparse scatter-add (vectorized reductions)
    int sblocks = (int)(((long long)NE * 64 + 255) / 256);
    scatter_kernel<<<sblocks, blk>>>(sup0, v0, r0, c0, a0);
    scatter_kernel<<<sblocks, blk>>>(sup1, v1, r1, c1, a1);

    // MLP branch 0: a0 -> b0 -> a0 -> b0
    mma_gemm<true, true><<<gT, blk, SMEMT>>>(
        a0, nullptr, mwt0,             mb0,       b0, NT, 256, 256);
    mma_gemm<true, true><<<gT, blk, SMEMT>>>(
        b0, nullptr, mwt0 + 65536,     mb0 + 256, a0, NT, 256, 256);
    mma_gemm<true, true><<<gT, blk, SMEMT>>>(
        a0, nullptr, mwt0 + 2 * 65536, mb0 + 512, b0, NT, 256, 256);

    // MLP branch 1: a1 -> b1 -> a1 -> b1
    mma_gemm<true, true><<<gT, blk, SMEMT>>>(
        a1, nullptr, mwt1,             mb1,       b1, NT, 256, 256);
    mma_gemm<true, true><<<gT, blk, SMEMT>>>(
        b1, nullptr, mwt1 + 65536,     mb1 + 256, a1, NT, 256, 256);
    mma_gemm<true, true><<<gT, blk, SMEMT>>>(
        a1, nullptr, mwt1 + 2 * 65536, mb1 + 512, b1, NT, 256, 256);

    // merge: out = [h0, h1] @ Wm + bm   (single K=512 GEMM, dual A sources)
    mma_gemm<true, false><<<gT, blk, SMEMT>>>(
        b0, b1, wmt, bmv, out, NT, 512, 256);
}

// round 11
// speedup vs baseline: 1.4393x; 1.0583x over previous
#include <cuda_runtime.h>
#include <cuda_fp16.h>
#include <cstdint>

// Problem constants
#define NT 50000
#define NS 100000
#define NE 400000
#define CIN 128
#define CCH 256

// ---------------------------------------------------------------------------
// Scratch (device globals — no allocation allowed)
// ---------------------------------------------------------------------------
__device__ float g_sup0[(size_t)NS * CCH];   // front half aliased as fp16 support
__device__ float g_sup1[(size_t)NS * CCH];
__device__ float g_a0[(size_t)NT * CCH];
__device__ float g_b0[(size_t)NT * CCH];
__device__ float g_a1[(size_t)NT * CCH];
__device__ float g_b1[(size_t)NT * CCH];
// fp16 transposed weights: [N=256, K] K-major (single rounding; A carries the split)
__device__ __half g_wt0[256 * 128];        // W0^T
__device__ __half g_wt1[256 * 128];        // W1^T
__device__ __half g_mwt0[3 * 256 * 256];   // per-layer
__device__ __half g_mwt1[3 * 256 * 256];
__device__ __half g_wmt[256 * 512];        // Wm^T (K=512)

// ---------------------------------------------------------------------------
// Helpers
// ---------------------------------------------------------------------------
__device__ __forceinline__ uint32_t smem_u32(const void* p) {
    uint32_t a;
    asm("{ .reg .u64 t; cvta.to.shared.u64 t, %1; cvt.u32.u64 %0, t; }"
        : "=r"(a) : "l"(p));
    return a;
}

__device__ __forceinline__ void ldsm4(uint32_t* r, uint32_t addr) {
    asm volatile("ldmatrix.sync.aligned.m8n8.x4.shared.b16 {%0,%1,%2,%3}, [%4];"
                 : "=r"(r[0]), "=r"(r[1]), "=r"(r[2]), "=r"(r[3]) : "r"(addr));
}

__device__ __forceinline__ void mma16816(float* d, const uint32_t* a, const uint32_t* b) {
    asm volatile(
        "mma.sync.aligned.m16n8k16.row.col.f32.f16.f16.f32 "
        "{%0,%1,%2,%3}, {%4,%5,%6,%7}, {%8,%9}, {%0,%1,%2,%3};"
        : "+f"(d[0]), "+f"(d[1]), "+f"(d[2]), "+f"(d[3])
        : "r"(a[0]), "r"(a[1]), "r"(a[2]), "r"(a[3]), "r"(b[0]), "r"(b[1]));
}

__device__ __forceinline__ uint32_t pack2h(__half x, __half y) {
    return ((uint32_t)__half_as_ushort(y) << 16) | __half_as_ushort(x);
}

// ---------------------------------------------------------------------------
// Weight prep: W [K, 256] fp32 -> Wt [256, K] fp16 (K-major, single rounding)
// Batched over grid.y layers
// ---------------------------------------------------------------------------
__global__ __launch_bounds__(256) void prep_w(
    const float* __restrict__ W, __half* __restrict__ Wt, int K)
{
    int l = blockIdx.y;
    const float* Wl = W + (size_t)l * K * 256;
    __half* Wtl = Wt + (size_t)l * K * 256;
    int idx = blockIdx.x * 256 + threadIdx.x;
    if (idx >= K * 256) return;
    int k = idx >> 8;
    int n = idx & 255;
    Wtl[(size_t)n * K + k] = __float2half(Wl[idx]);
}

// ---------------------------------------------------------------------------
// Split-fp16 mma.sync GEMM:  C[M,256] = relu?( A[M,Ktot] @ Bt^T + bias )
// A fp32, split on the fly into exact fp16 hi/lo (2 MMAs per product).
// Bt pre-rounded fp16 [256, Ktot] K-major.
// Dual-branch batching: blockIdx.x >= xblocks selects the 'b' pointer set.
// A2: optional second fp32 A source for k >= 256 (merge GEMM, Ktot=512).
// OUTH: C stored as fp16 (support); else fp32.
// Block: 256 thr, tile 128x128, BK=32, double-buffered smem, occ 2.
// ---------------------------------------------------------------------------
#define ROWB 80
#define BUF  (128 * ROWB)          /* 10240 B per operand buffer  */
#define STAGE (3 * BUF)            /* AH, AL, B = 30720 B          */
#define SMEMT (2 * STAGE)          /* 61440 B                      */

template <bool OUTH, bool BIAS, bool RELU>
__global__ __launch_bounds__(256, 2) void mma_gemm(
    const float* __restrict__ Aa, const float* __restrict__ Ab,
    const float* __restrict__ A2a, const float* __restrict__ A2b,
    const __half* __restrict__ Ba, const __half* __restrict__ Bb,
    const float* __restrict__ biasa, const float* __restrict__ biasb,
    void* __restrict__ Ca, void* __restrict__ Cb,
    int M, int Ktot, int lda, int xblocks)
{
    extern __shared__ char smem[];
    const uint32_t sb = smem_u32(smem);
    const int tid = threadIdx.x;
    const int wid = tid >> 5;
    const int lane = tid & 31;
    const int warpM = wid >> 2;
    const int warpN = wid & 3;
    int bx = blockIdx.x;
    const bool sec = (bx >= xblocks);
    if (sec) bx -= xblocks;
    const int bm = bx * 128;
    const int bn = blockIdx.y * 128;
    const float* A  = sec ? Ab  : Aa;
    const float* A2 = sec ? A2b : A2a;
    const __half* Bt = sec ? Bb : Ba;
    const float* bias = sec ? biasb : biasa;
    void* C = sec ? Cb : Ca;

    float acc[4][4][4];
#pragma unroll
    for (int i = 0; i < 4; i++)
#pragma unroll
        for (int j = 0; j < 4; j++)
#pragma unroll
            for (int q = 0; q < 4; q++) acc[i][j][q] = 0.0f;

    float4 aReg[4];
    uint4 bReg[2];

    auto loadG = [&](int c) {
        const int k0 = c << 5;
        const float* Ap = A;
        int kk = k0;
        if (A2 != nullptr && k0 >= 256) { Ap = A2; kk = k0 - 256; }
#pragma unroll
        for (int i = 0; i < 4; i++) {
            int idx = i * 256 + tid;
            int r = idx >> 3, c4 = idx & 7;
            int row = bm + r;
            aReg[i] = (row < M)
                ? __ldg((const float4*)(Ap + (size_t)row * lda + kk) + c4)
                : make_float4(0.f, 0.f, 0.f, 0.f);
        }
#pragma unroll
        for (int i = 0; i < 2; i++) {
            int idx = i * 256 + tid;
            int r = idx >> 2, ch = idx & 3;
            size_t g = (size_t)(bn + r) * Ktot + k0 + ch * 8;
            bReg[i] = __ldg((const uint4*)(Bt + g));
        }
    };

    auto storeS = [&](int s) {
        char* st = smem + s * STAGE;
#pragma unroll
        for (int i = 0; i < 4; i++) {
            int idx = i * 256 + tid;
            int r = idx >> 3, c4 = idx & 7;
            uint32_t off = (uint32_t)(r * ROWB + c4 * 8);
            float4 v = aReg[i];
            __half h0 = __float2half(v.x);
            __half h1 = __float2half(v.y);
            __half h2 = __float2half(v.z);
            __half h3 = __float2half(v.w);
            uint2 ph, pl;
            ph.x = pack2h(h0, h1);
            ph.y = pack2h(h2, h3);
            pl.x = pack2h(__float2half(v.x - __half2float(h0)),
                          __float2half(v.y - __half2float(h1)));
            pl.y = pack2h(__float2half(v.z - __half2float(h2)),
                          __float2half(v.w - __half2float(h3)));
            *(uint2*)(st + off) = ph;
            *(uint2*)(st + BUF + off) = pl;
        }
#pragma unroll
        for (int i = 0; i < 2; i++) {
            int idx = i * 256 + tid;
            int r = idx >> 2, ch = idx & 3;
            uint32_t off = (uint32_t)(r * ROWB + ch * 16);
            *(uint4*)(st + 2 * BUF + off) = bReg[i];
        }
    };

    auto mmaS = [&](int s) {
        const uint32_t base = sb + s * STAGE;
#pragma unroll
        for (int ks = 0; ks < 2; ks++) {
            uint32_t bf[4][2];
#pragma unroll
            for (int ntp = 0; ntp < 2; ntp++) {
                int rB = warpN * 32 + ntp * 16 + ((lane >> 4) & 1) * 8 + (lane & 7);
                int cB = ks * 2 + ((lane >> 3) & 1);
                uint32_t addr = base + 2 * BUF + rB * ROWB + cB * 16;
                uint32_t q[4];
                ldsm4(q, addr);
                bf[ntp * 2][0] = q[0]; bf[ntp * 2][1] = q[1];
                bf[ntp * 2 + 1][0] = q[2]; bf[ntp * 2 + 1][1] = q[3];
            }
#pragma unroll
            for (int mt = 0; mt < 4; mt++) {
                int rA = warpM * 64 + mt * 16 + (lane & 15);
                int cA = ks * 2 + (lane >> 4);
                uint32_t addr = base + rA * ROWB + cA * 16;
                uint32_t ah[4], al[4];
                ldsm4(ah, addr);
                ldsm4(al, addr + BUF);
#pragma unroll
                for (int nt = 0; nt < 4; nt++) {
                    mma16816(acc[mt][nt], ah, bf[nt]);
                    mma16816(acc[mt][nt], al, bf[nt]);
                }
            }
        }
    };

    const int nch = Ktot >> 5;
    loadG(0);
    storeS(0);
    __syncthreads();
    for (int c = 0; c < nch; c++) {
        if (c + 1 < nch) loadG(c + 1);
        mmaS(c & 1);
        if (c + 1 < nch) storeS((c + 1) & 1);
        __syncthreads();
    }

    // Epilogue
#pragma unroll
    for (int mt = 0; mt < 4; mt++) {
        int row0 = bm + warpM * 64 + mt * 16 + (lane >> 2);
#pragma unroll
        for (int nt = 0; nt < 4; nt++) {
            int col = bn + warpN * 32 + nt * 8 + (lane & 3) * 2;
            float bx2 = 0.f, by2 = 0.f;
            if (BIAS) { bx2 = __ldg(bias + col); by2 = __ldg(bias + col + 1); }
            float2 v0 = make_float2(acc[mt][nt][0] + bx2, acc[mt][nt][1] + by2);
            float2 v1 = make_float2(acc[mt][nt][2] + bx2, acc[mt][nt][3] + by2);
            if (RELU) {
                v0.x = fmaxf(v0.x, 0.f); v0.y = fmaxf(v0.y, 0.f);
                v1.x = fmaxf(v1.x, 0.f); v1.y = fmaxf(v1.y, 0.f);
            }
            if (OUTH) {
                __half* Ch = (__half*)C;
                if (row0 < M)
                    *(uint32_t*)(Ch + (size_t)row0 * 256 + col) =
                        pack2h(__float2half(v0.x), __float2half(v0.y));
                if (row0 + 8 < M)
                    *(uint32_t*)(Ch + (size_t)(row0 + 8) * 256 + col) =
                        pack2h(__float2half(v1.x), __float2half(v1.y));
            } else {
                float* Cf = (float*)C;
                if (row0 < M)     *(float2*)(Cf + (size_t)row0 * 256 + col) = v0;
                if (row0 + 8 < M) *(float2*)(Cf + (size_t)(row0 + 8) * 256 + col) = v1;
            }
        }
    }
}

// ---------------------------------------------------------------------------
// Edge scatter: agg[rows[e]] += vals[e] * support_fp16[cols[e]]  (256 ch)
// 64 threads/edge, 8B fp16 gather + one red.global.add.v4.f32 per 16B.
// ---------------------------------------------------------------------------
__global__ __launch_bounds__(256) void scatter_kernel(
    const __half* __restrict__ sup, const float* __restrict__ vals,
    const int* __restrict__ rows, const int* __restrict__ cols,
    float* __restrict__ agg)
{
    long long idx = (long long)blockIdx.x * blockDim.x + threadIdx.x;
    if (idx >= (long long)NE * 64) return;
    int e = (int)(idx >> 6);
    int q = (int)(idx & 63);
    int r = __ldg(rows + e);
    int c = __ldg(cols + e);
    float v = __ldg(vals + e);
    uint2 s = __ldg((const uint2*)(sup + (size_t)c * CCH) + q);
    float2 f01 = __half22float2(*(const __half2*)&s.x);
    float2 f23 = __half22float2(*(const __half2*)&s.y);
    float* dst = agg + (size_t)r * CCH + q * 4;
    asm volatile("red.global.add.v4.f32 [%0], {%1, %2, %3, %4};"
                 :: "l"(dst), "f"(v * f01.x), "f"(v * f01.y),
                    "f"(v * f23.x), "f"(v * f23.y)
                 : "memory");
}

// ---------------------------------------------------------------------------
extern "C" void kernel_launch(void* const* d_in, const int* in_sizes, int n_in,
                              void* d_out, int out_size)
{
    const float* x_t  = (const float*)d_in[0];
    const float* xs0  = (const float*)d_in[1];
    const float* xs1  = (const float*)d_in[2];
    const float* v0   = (const float*)d_in[3];
    const float* v1   = (const float*)d_in[4];
    const int*   r0   = (const int*)d_in[5];
    const int*   c0   = (const int*)d_in[6];
    const int*   r1   = (const int*)d_in[7];
    const int*   c1   = (const int*)d_in[8];
    const float* W0   = (const float*)d_in[9];
    const float* W1   = (const float*)d_in[10];
    const float* mW0  = (const float*)d_in[11];
    const float* mb0  = (const float*)d_in[12];
    const float* mW1  = (const float*)d_in[13];
    const float* mb1  = (const float*)d_in[14];
    const float* Wm   = (const float*)d_in[15];
    const float* bmv  = (const float*)d_in[16];
    float* out = (float*)d_out;

    float *sup0f, *sup1f, *a0, *b0, *a1, *b1;
    __half *wt0, *wt1, *mwt0, *mwt1, *wmt;
    cudaGetSymbolAddress((void**)&sup0f, g_sup0);
    cudaGetSymbolAddress((void**)&sup1f, g_sup1);
    cudaGetSymbolAddress((void**)&a0, g_a0);
    cudaGetSymbolAddress((void**)&b0, g_b0);
    cudaGetSymbolAddress((void**)&a1, g_a1);
    cudaGetSymbolAddress((void**)&b1, g_b1);
    cudaGetSymbolAddress((void**)&wt0, g_wt0);
    cudaGetSymbolAddress((void**)&wt1, g_wt1);
    cudaGetSymbolAddress((void**)&mwt0, g_mwt0);
    cudaGetSymbolAddress((void**)&mwt1, g_mwt1);
    cudaGetSymbolAddress((void**)&wmt, g_wmt);

    __half* sup0 = (__half*)sup0f;   // fp16 support aliased into fp32 scratch
    __half* sup1 = (__half*)sup1f;

    cudaFuncSetAttribute(mma_gemm<true, false, false>,
                         cudaFuncAttributeMaxDynamicSharedMemorySize, SMEMT);
    cudaFuncSetAttribute(mma_gemm<false, true, true>,
                         cudaFuncAttributeMaxDynamicSharedMemorySize, SMEMT);
    cudaFuncSetAttribute(mma_gemm<false, true, false>,
                         cudaFuncAttributeMaxDynamicSharedMemorySize, SMEMT);

    // ---- Weight prep: transpose + fp16 round (batched) ----
    dim3 gp1((128 * 256 + 255) / 256, 1);
    prep_w<<<gp1, 256>>>(W0, wt0, 128);
    prep_w<<<gp1, 256>>>(W1, wt1, 128);
    dim3 gp3((256 * 256 + 255) / 256, 3);
    prep_w<<<gp3, 256>>>(mW0, mwt0, 256);
    prep_w<<<gp3, 256>>>(mW1, mwt1, 256);
    dim3 gpm((512 * 256 + 255) / 256, 1);
    prep_w<<<gpm, 256>>>(Wm, wmt, 512);

    dim3 blk(256);
    const int xS = (NS + 127) / 128;   // 782
    const int xT = (NT + 127) / 128;   // 391
    dim3 gS(2 * xS, 2);                // both branches, one launch
    dim3 gT(2 * xT, 2);
    dim3 gM(xT, 2);

    // support = x_src @ W  (fp16 output, both branches)
    mma_gemm<true, false, false><<<gS, blk, SMEMT>>>(
        xs0, xs1, nullptr, nullptr, wt0, wt1, nullptr, nullptr,
        sup0, sup1, NS, 128, 128, xS);

    // agg init = x_target (epsilon = 0)
    cudaMemcpyAsync(a0, x_t, sizeof(float) * (size_t)NT * CCH, cudaMemcpyDeviceToDevice);
    cudaMemcpyAsync(a1, x_t, sizeof(float) * (size_t)NT * CCH, cudaMemcpyDeviceToDevice);

    // sparse scatter-add (fp16 gather, fp32 vectorized reductions)
    int sblocks = (int)(((long long)NE * 64 + 255) / 256);
    scatter_kernel<<<sblocks, blk>>>(sup0, v0, r0, c0, a0);
    scatter_kernel<<<sblocks, blk>>>(sup1, v1, r1, c1, a1);

    // MLP layers (both branches per launch): a -> b -> a -> b
    mma_gemm<false, true, true><<<gT, blk, SMEMT>>>(
        a0, a1, nullptr, nullptr, mwt0, mwt1, mb0, mb1,
        b0, b1, NT, 256, 256, xT);
    mma_gemm<false, true, true><<<gT, blk, SMEMT>>>(
        b0, b1, nullptr, nullptr, mwt0 + 65536, mwt1 + 65536,
        mb0 + 256, mb1 + 256, a0, a1, NT, 256, 256, xT);
    mma_gemm<false, true, true><<<gT, blk, SMEMT>>>(
        a0, a1, nullptr, nullptr, mwt0 + 2 * 65536, mwt1 + 2 * 65536,
        mb0 + 512, mb1 + 512, b0, b1, NT, 256, 256, xT);

    // merge: out = [h0, h1] @ Wm + bm  (single K=512 GEMM, dual A sources)
    mma_gemm<false, true, false><<<gM, blk, SMEMT>>>(
        b0, nullptr, b1, nullptr, wmt, nullptr, bmv, nullptr,
        out, nullptr, NT, 512, 256, xT);
}

// round 12
// speedup vs baseline: 1.5362x; 1.0674x over previous
#include <cuda_runtime.h>
#include <cuda_fp16.h>
#include <cstdint>

// Problem constants
#define NT 50000
#define NS 100000
#define NE 400000
#define CIN 128
#define CCH 256

// ---------------------------------------------------------------------------
// Scratch (device globals — no allocation allowed)
// ---------------------------------------------------------------------------
__device__ float g_sup0[(size_t)NS * CCH];   // aliased fp16 support
__device__ float g_sup1[(size_t)NS * CCH];
__device__ float g_a0[(size_t)NT * CCH];
__device__ float g_b0[(size_t)NT * CCH];     // layer outputs; fp16 h after L3
__device__ float g_a1[(size_t)NT * CCH];
__device__ float g_b1[(size_t)NT * CCH];
// fp16 transposed weights: [N=256, K] K-major
__device__ __half g_wt0[256 * 128];
__device__ __half g_wt1[256 * 128];
__device__ __half g_mwt0[3 * 256 * 256];
__device__ __half g_mwt1[3 * 256 * 256];
__device__ __half g_wmt[256 * 512];

// ---------------------------------------------------------------------------
// Helpers
// ---------------------------------------------------------------------------
__device__ __forceinline__ uint32_t smem_u32(const void* p) {
    uint32_t a;
    asm("{ .reg .u64 t; cvta.to.shared.u64 t, %1; cvt.u32.u64 %0, t; }"
        : "=r"(a) : "l"(p));
    return a;
}

__device__ __forceinline__ void ldsm4(uint32_t* r, uint32_t addr) {
    asm volatile("ldmatrix.sync.aligned.m8n8.x4.shared.b16 {%0,%1,%2,%3}, [%4];"
                 : "=r"(r[0]), "=r"(r[1]), "=r"(r[2]), "=r"(r[3]) : "r"(addr));
}

__device__ __forceinline__ void mma16816(float* d, const uint32_t* a, const uint32_t* b) {
    asm volatile(
        "mma.sync.aligned.m16n8k16.row.col.f32.f16.f16.f32 "
        "{%0,%1,%2,%3}, {%4,%5,%6,%7}, {%8,%9}, {%0,%1,%2,%3};"
        : "+f"(d[0]), "+f"(d[1]), "+f"(d[2]), "+f"(d[3])
        : "r"(a[0]), "r"(a[1]), "r"(a[2]), "r"(a[3]), "r"(b[0]), "r"(b[1]));
}

__device__ __forceinline__ uint32_t pack2h(__half x, __half y) {
    return ((uint32_t)__half_as_ushort(y) << 16) | __half_as_ushort(x);
}

// ---------------------------------------------------------------------------
// Weight prep: W [K, 256] fp32 -> Wt [256, K] fp16 (K-major)
// ---------------------------------------------------------------------------
__global__ __launch_bounds__(256) void prep_w(
    const float* __restrict__ W, __half* __restrict__ Wt, int K)
{
    int l = blockIdx.y;
    const float* Wl = W + (size_t)l * K * 256;
    __half* Wtl = Wt + (size_t)l * K * 256;
    int idx = blockIdx.x * 256 + threadIdx.x;
    if (idx >= K * 256) return;
    int k = idx >> 8;
    int n = idx & 255;
    Wtl[(size_t)n * K + k] = __float2half(Wl[idx]);
}

// ---------------------------------------------------------------------------
// Fused agg init: a0 = a1 = x_target  (single read, two writes)
// ---------------------------------------------------------------------------
__global__ __launch_bounds__(256) void init_agg(
    const float* __restrict__ x, float* __restrict__ a0, float* __restrict__ a1)
{
    size_t i = (size_t)blockIdx.x * 256 + threadIdx.x;
    if (i >= (size_t)NT * CCH / 4) return;
    float4 v = __ldg((const float4*)x + i);
    ((float4*)a0)[i] = v;
    ((float4*)a1)[i] = v;
}

// ---------------------------------------------------------------------------
// mma.sync GEMM, AMODE: 0 = fp32 A, exact hi/lo split (2 MMA)
//                       1 = fp32 A, plain fp16 round   (1 MMA)
//                       2 = fp16 A, direct             (1 MMA)
// Bt pre-rounded fp16 [256, Ktot] K-major.
// Dual-branch batching: blockIdx.x >= xblocks selects 'b' pointer set.
// A2: second A source for k >= 256 (merge, Ktot=512).
// OUTH: C stored fp16; else fp32.
// Block: 256 thr, tile 128x128, BK=32, double-buffered smem, occ 2.
// ---------------------------------------------------------------------------
#define ROWB 80
#define BUF  (128 * ROWB)
#define STAGE (3 * BUF)
#define SMEMT (2 * STAGE)

template <int AMODE, bool OUTH, bool BIAS, bool RELU>
__global__ __launch_bounds__(256, 2) void mma_gemm(
    const void* __restrict__ Aa, const void* __restrict__ Ab,
    const void* __restrict__ A2a, const void* __restrict__ A2b,
    const __half* __restrict__ Ba, const __half* __restrict__ Bb,
    const float* __restrict__ biasa, const float* __restrict__ biasb,
    void* __restrict__ Ca, void* __restrict__ Cb,
    int M, int Ktot, int lda, int xblocks)
{
    extern __shared__ char smem[];
    const uint32_t sb = smem_u32(smem);
    const int tid = threadIdx.x;
    const int wid = tid >> 5;
    const int lane = tid & 31;
    const int warpM = wid >> 2;
    const int warpN = wid & 3;
    int bx = blockIdx.x;
    const bool sec = (bx >= xblocks);
    if (sec) bx -= xblocks;
    const int bm = bx * 128;
    const int bn = blockIdx.y * 128;
    const void* A  = sec ? Ab  : Aa;
    const void* A2 = sec ? A2b : A2a;
    const __half* Bt = sec ? Bb : Ba;
    const float* bias = sec ? biasb : biasa;
    void* C = sec ? Cb : Ca;

    float acc[4][4][4];
#pragma unroll
    for (int i = 0; i < 4; i++)
#pragma unroll
        for (int j = 0; j < 4; j++)
#pragma unroll
            for (int q = 0; q < 4; q++) acc[i][j][q] = 0.0f;

    float4 aReg[4];      // AMODE 0/1
    uint4 ahReg[2];      // AMODE 2
    uint4 bReg[2];

    auto loadG = [&](int c) {
        const int k0 = c << 5;
        const void* Ap = A;
        int kk = k0;
        if (A2 != nullptr && k0 >= 256) { Ap = A2; kk = k0 - 256; }
        if (AMODE == 2) {
            const __half* Ah = (const __half*)Ap;
#pragma unroll
            for (int i = 0; i < 2; i++) {
                int idx = i * 256 + tid;
                int r = idx >> 2, ch = idx & 3;
                int row = bm + r;
                ahReg[i] = (row < M)
                    ? __ldg((const uint4*)(Ah + (size_t)row * lda + kk) + ch)
                    : make_uint4(0, 0, 0, 0);
            }
        } else {
            const float* Af = (const float*)Ap;
#pragma unroll
            for (int i = 0; i < 4; i++) {
                int idx = i * 256 + tid;
                int r = idx >> 3, c4 = idx & 7;
                int row = bm + r;
                aReg[i] = (row < M)
                    ? __ldg((const float4*)(Af + (size_t)row * lda + kk) + c4)
                    : make_float4(0.f, 0.f, 0.f, 0.f);
            }
        }
#pragma unroll
        for (int i = 0; i < 2; i++) {
            int idx = i * 256 + tid;
            int r = idx >> 2, ch = idx & 3;
            size_t g = (size_t)(bn + r) * Ktot + k0 + ch * 8;
            bReg[i] = __ldg((const uint4*)(Bt + g));
        }
    };

    auto storeS = [&](int s) {
        char* st = smem + s * STAGE;
        if (AMODE == 2) {
#pragma unroll
            for (int i = 0; i < 2; i++) {
                int idx = i * 256 + tid;
                int r = idx >> 2, ch = idx & 3;
                *(uint4*)(st + r * ROWB + ch * 16) = ahReg[i];
            }
        } else {
#pragma unroll
            for (int i = 0; i < 4; i++) {
                int idx = i * 256 + tid;
                int r = idx >> 3, c4 = idx & 7;
                uint32_t off = (uint32_t)(r * ROWB + c4 * 8);
                float4 v = aReg[i];
                __half h0 = __float2half(v.x);
                __half h1 = __float2half(v.y);
                __half h2 = __float2half(v.z);
                __half h3 = __float2half(v.w);
                uint2 ph;
                ph.x = pack2h(h0, h1);
                ph.y = pack2h(h2, h3);
                *(uint2*)(st + off) = ph;
                if (AMODE == 0) {
                    uint2 pl;
                    pl.x = pack2h(__float2half(v.x - __half2float(h0)),
                                  __float2half(v.y - __half2float(h1)));
                    pl.y = pack2h(__float2half(v.z - __half2float(h2)),
                                  __float2half(v.w - __half2float(h3)));
                    *(uint2*)(st + BUF + off) = pl;
                }
            }
        }
#pragma unroll
        for (int i = 0; i < 2; i++) {
            int idx = i * 256 + tid;
            int r = idx >> 2, ch = idx & 3;
            *(uint4*)(st + 2 * BUF + r * ROWB + ch * 16) = bReg[i];
        }
    };

    auto mmaS = [&](int s) {
        const uint32_t base = sb + s * STAGE;
#pragma unroll
        for (int ks = 0; ks < 2; ks++) {
            uint32_t bf[4][2];
#pragma unroll
            for (int ntp = 0; ntp < 2; ntp++) {
                int rB = warpN * 32 + ntp * 16 + ((lane >> 4) & 1) * 8 + (lane & 7);
                int cB = ks * 2 + ((lane >> 3) & 1);
                uint32_t addr = base + 2 * BUF + rB * ROWB + cB * 16;
                uint32_t q[4];
                ldsm4(q, addr);
                bf[ntp * 2][0] = q[0]; bf[ntp * 2][1] = q[1];
                bf[ntp * 2 + 1][0] = q[2]; bf[ntp * 2 + 1][1] = q[3];
            }
#pragma unroll
            for (int mt = 0; mt < 4; mt++) {
                int rA = warpM * 64 + mt * 16 + (lane & 15);
                int cA = ks * 2 + (lane >> 4);
                uint32_t addr = base + rA * ROWB + cA * 16;
                uint32_t ah[4];
                ldsm4(ah, addr);
#pragma unroll
                for (int nt = 0; nt < 4; nt++)
                    mma16816(acc[mt][nt], ah, bf[nt]);
                if (AMODE == 0) {
                    uint32_t al[4];
                    ldsm4(al, addr + BUF);
#pragma unroll
                    for (int nt = 0; nt < 4; nt++)
                        mma16816(acc[mt][nt], al, bf[nt]);
                }
            }
        }
    };

    const int nch = Ktot >> 5;
    loadG(0);
    storeS(0);
    __syncthreads();
    for (int c = 0; c < nch; c++) {
        if (c + 1 < nch) loadG(c + 1);
        mmaS(c & 1);
        if (c + 1 < nch) storeS((c + 1) & 1);
        __syncthreads();
    }

    // Epilogue
#pragma unroll
    for (int mt = 0; mt < 4; mt++) {
        int row0 = bm + warpM * 64 + mt * 16 + (lane >> 2);
#pragma unroll
        for (int nt = 0; nt < 4; nt++) {
            int col = bn + warpN * 32 + nt * 8 + (lane & 3) * 2;
            float bx2 = 0.f, by2 = 0.f;
            if (BIAS) { bx2 = __ldg(bias + col); by2 = __ldg(bias + col + 1); }
            float2 v0 = make_float2(acc[mt][nt][0] + bx2, acc[mt][nt][1] + by2);
            float2 v1 = make_float2(acc[mt][nt][2] + bx2, acc[mt][nt][3] + by2);
            if (RELU) {
                v0.x = fmaxf(v0.x, 0.f); v0.y = fmaxf(v0.y, 0.f);
                v1.x = fmaxf(v1.x, 0.f); v1.y = fmaxf(v1.y, 0.f);
            }
            if (OUTH) {
                __half* Ch = (__half*)C;
                if (row0 < M)
                    *(uint32_t*)(Ch + (size_t)row0 * 256 + col) =
                        pack2h(__float2half(v0.x), __float2half(v0.y));
                if (row0 + 8 < M)
                    *(uint32_t*)(Ch + (size_t)(row0 + 8) * 256 + col) =
                        pack2h(__float2half(v1.x), __float2half(v1.y));
            } else {
                float* Cf = (float*)C;
                if (row0 < M)     *(float2*)(Cf + (size_t)row0 * 256 + col) = v0;
                if (row0 + 8 < M) *(float2*)(Cf + (size_t)(row0 + 8) * 256 + col) = v1;
            }
        }
    }
}

// ---------------------------------------------------------------------------
// Combined edge scatter (both branches, one launch for latency hiding):
// agg[rows[e]] += vals[e] * support_fp16[cols[e]]  (256 ch, 64 thr/edge)
// ---------------------------------------------------------------------------
__global__ __launch_bounds__(256) void scatter_kernel(
    const __half* __restrict__ sup0, const __half* __restrict__ sup1,
    const float* __restrict__ v0, const float* __restrict__ v1,
    const int* __restrict__ r0, const int* __restrict__ r1,
    const int* __restrict__ c0, const int* __restrict__ c1,
    float* __restrict__ a0, float* __restrict__ a1)
{
    long long idx = (long long)blockIdx.x * blockDim.x + threadIdx.x;
    const long long half = (long long)NE * 64;
    if (idx >= 2 * half) return;
    const bool b1 = (idx >= half);
    if (b1) idx -= half;
    const __half* sup = b1 ? sup1 : sup0;
    const float* vals = b1 ? v1 : v0;
    const int* rows = b1 ? r1 : r0;
    const int* cols = b1 ? c1 : c0;
    float* agg = b1 ? a1 : a0;

    int e = (int)(idx >> 6);
    int q = (int)(idx & 63);
    int r = __ldg(rows + e);
    int c = __ldg(cols + e);
    float v = __ldg(vals + e);
    uint2 s = __ldg((const uint2*)(sup + (size_t)c * CCH) + q);
    float2 f01 = __half22float2(*(const __half2*)&s.x);
    float2 f23 = __half22float2(*(const __half2*)&s.y);
    float* dst = agg + (size_t)r * CCH + q * 4;
    asm volatile("red.global.add.v4.f32 [%0], {%1, %2, %3, %4};"
                 :: "l"(dst), "f"(v * f01.x), "f"(v * f01.y),
                    "f"(v * f23.x), "f"(v * f23.y)
                 : "memory");
}

// ---------------------------------------------------------------------------
extern "C" void kernel_launch(void* const* d_in, const int* in_sizes, int n_in,
                              void* d_out, int out_size)
{
    const float* x_t  = (const float*)d_in[0];
    const float* xs0  = (const float*)d_in[1];
    const float* xs1  = (const float*)d_in[2];
    const float* v0   = (const float*)d_in[3];
    const float* v1   = (const float*)d_in[4];
    const int*   r0   = (const int*)d_in[5];
    const int*   c0   = (const int*)d_in[6];
    const int*   r1   = (const int*)d_in[7];
    const int*   c1   = (const int*)d_in[8];
    const float* W0   = (const float*)d_in[9];
    const float* W1   = (const float*)d_in[10];
    const float* mW0  = (const float*)d_in[11];
    const float* mb0  = (const float*)d_in[12];
    const float* mW1  = (const float*)d_in[13];
    const float* mb1  = (const float*)d_in[14];
    const float* Wm   = (const float*)d_in[15];
    const float* bmv  = (const float*)d_in[16];
    float* out = (float*)d_out;

    float *sup0f, *sup1f, *a0, *b0, *a1, *b1;
    __half *wt0, *wt1, *mwt0, *mwt1, *wmt;
    cudaGetSymbolAddress((void**)&sup0f, g_sup0);
    cudaGetSymbolAddress((void**)&sup1f, g_sup1);
    cudaGetSymbolAddress((void**)&a0, g_a0);
    cudaGetSymbolAddress((void**)&b0, g_b0);
    cudaGetSymbolAddress((void**)&a1, g_a1);
    cudaGetSymbolAddress((void**)&b1, g_b1);
    cudaGetSymbolAddress((void**)&wt0, g_wt0);
    cudaGetSymbolAddress((void**)&wt1, g_wt1);
    cudaGetSymbolAddress((void**)&mwt0, g_mwt0);
    cudaGetSymbolAddress((void**)&mwt1, g_mwt1);
    cudaGetSymbolAddress((void**)&wmt, g_wmt);

    __half* sup0 = (__half*)sup0f;
    __half* sup1 = (__half*)sup1f;
    __half* h0 = (__half*)b0;   // fp16 layer-3 output aliased into b buffers
    __half* h1 = (__half*)b1;

    cudaFuncSetAttribute(mma_gemm<1, true, false, false>,
                         cudaFuncAttributeMaxDynamicSharedMemorySize, SMEMT);
    cudaFuncSetAttribute(mma_gemm<0, false, true, true>,
                         cudaFuncAttributeMaxDynamicSharedMemorySize, SMEMT);
    cudaFuncSetAttribute(mma_gemm<0, true, true, true>,
                         cudaFuncAttributeMaxDynamicSharedMemorySize, SMEMT);
    cudaFuncSetAttribute(mma_gemm<2, false, true, false>,
                         cudaFuncAttributeMaxDynamicSharedMemorySize, SMEMT);

    // ---- Weight prep ----
    dim3 gp1((128 * 256 + 255) / 256, 1);
    prep_w<<<gp1, 256>>>(W0, wt0, 128);
    prep_w<<<gp1, 256>>>(W1, wt1, 128);
    dim3 gp3((256 * 256 + 255) / 256, 3);
    prep_w<<<gp3, 256>>>(mW0, mwt0, 256);
    prep_w<<<gp3, 256>>>(mW1, mwt1, 256);
    dim3 gpm((512 * 256 + 255) / 256, 1);
    prep_w<<<gpm, 256>>>(Wm, wmt, 512);

    dim3 blk(256);
    const int xS = (NS + 127) / 128;   // 782
    const int xT = (NT + 127) / 128;   // 391
    dim3 gS(2 * xS, 2);
    dim3 gT(2 * xT, 2);
    dim3 gM(xT, 2);

    // support = fp16(x_src) @ W  (1-MMA path, fp16 output, both branches)
    mma_gemm<1, true, false, false><<<gS, blk, SMEMT>>>(
        xs0, xs1, nullptr, nullptr, wt0, wt1, nullptr, nullptr,
        sup0, sup1, NS, 128, 128, xS);

    // agg init = x_target (epsilon = 0), fused
    init_agg<<<(int)(((size_t)NT * CCH / 4 + 255) / 256), blk>>>(x_t, a0, a1);

    // combined sparse scatter-add (both branches, one launch)
    long long tot = 2LL * NE * 64;
    scatter_kernel<<<(int)((tot + 255) / 256), blk>>>(
        sup0, sup1, v0, v1, r0, r1, c0, c1, a0, a1);

    // MLP layer 1: a (fp32) -> b (fp32), split A
    mma_gemm<0, false, true, true><<<gT, blk, SMEMT>>>(
        a0, a1, nullptr, nullptr, mwt0, mwt1, mb0, mb1,
        b0, b1, NT, 256, 256, xT);
    // MLP layer 2: b -> a
    mma_gemm<0, false, true, true><<<gT, blk, SMEMT>>>(
        b0, b1, nullptr, nullptr, mwt0 + 65536, mwt1 + 65536,
        mb0 + 256, mb1 + 256, a0, a1, NT, 256, 256, xT);
    // MLP layer 3: a -> h (fp16 output)
    mma_gemm<0, true, true, true><<<gT, blk, SMEMT>>>(
        a0, a1, nullptr, nullptr, mwt0 + 2 * 65536, mwt1 + 2 * 65536,
        mb0 + 512, mb1 + 512, h0, h1, NT, 256, 256, xT);

    // merge: out = [h0, h1] @ Wm + bm  (fp16 A direct, K=512)
    mma_gemm<2, false, true, false><<<gM, blk, SMEMT>>>(
        h0, nullptr, h1, nullptr, wmt, nullptr, bmv, nullptr,
        out, nullptr, NT, 512, 256, xT);
}

// round 13
// speedup vs baseline: 1.7730x; 1.1541x over previous
#include <cuda_runtime.h>
#include <cuda_fp16.h>
#include <cstdint>

// Problem constants
#define NT 50000
#define NS 100000
#define NE 400000
#define CIN 128
#define CCH 256

// ---------------------------------------------------------------------------
// Scratch (device globals — no allocation allowed)
// ---------------------------------------------------------------------------
__device__ float g_sup0[(size_t)NS * CCH];   // aliased fp16 support
__device__ float g_sup1[(size_t)NS * CCH];
__device__ float g_a0[(size_t)NT * CCH];     // fp32 agg; later fp16 L2 out
__device__ float g_b0[(size_t)NT * CCH];     // fp16 L1/L3 out
__device__ float g_a1[(size_t)NT * CCH];
__device__ float g_b1[(size_t)NT * CCH];
// fp16 transposed weights: [N=256, K] K-major
__device__ __half g_wt0[256 * 128];
__device__ __half g_wt1[256 * 128];
__device__ __half g_mwt0[3 * 256 * 256];
__device__ __half g_mwt1[3 * 256 * 256];
__device__ __half g_wmt[256 * 512];

// ---------------------------------------------------------------------------
// Helpers
// ---------------------------------------------------------------------------
__device__ __forceinline__ uint32_t smem_u32(const void* p) {
    uint32_t a;
    asm("{ .reg .u64 t; cvta.to.shared.u64 t, %1; cvt.u32.u64 %0, t; }"
        : "=r"(a) : "l"(p));
    return a;
}

__device__ __forceinline__ void ldsm4(uint32_t* r, uint32_t addr) {
    asm volatile("ldmatrix.sync.aligned.m8n8.x4.shared.b16 {%0,%1,%2,%3}, [%4];"
                 : "=r"(r[0]), "=r"(r[1]), "=r"(r[2]), "=r"(r[3]) : "r"(addr));
}

__device__ __forceinline__ void mma16816(float* d, const uint32_t* a, const uint32_t* b) {
    asm volatile(
        "mma.sync.aligned.m16n8k16.row.col.f32.f16.f16.f32 "
        "{%0,%1,%2,%3}, {%4,%5,%6,%7}, {%8,%9}, {%0,%1,%2,%3};"
        : "+f"(d[0]), "+f"(d[1]), "+f"(d[2]), "+f"(d[3])
        : "r"(a[0]), "r"(a[1]), "r"(a[2]), "r"(a[3]), "r"(b[0]), "r"(b[1]));
}

__device__ __forceinline__ uint32_t pack2h(__half x, __half y) {
    return ((uint32_t)__half_as_ushort(y) << 16) | __half_as_ushort(x);
}

// ---------------------------------------------------------------------------
// Weight prep: W [K, 256] fp32 -> Wt [256, K] fp16 (K-major)
// ---------------------------------------------------------------------------
__global__ __launch_bounds__(256) void prep_w(
    const float* __restrict__ W, __half* __restrict__ Wt, int K)
{
    int l = blockIdx.y;
    const float* Wl = W + (size_t)l * K * 256;
    __half* Wtl = Wt + (size_t)l * K * 256;
    int idx = blockIdx.x * 256 + threadIdx.x;
    if (idx >= K * 256) return;
    int k = idx >> 8;
    int n = idx & 255;
    Wtl[(size_t)n * K + k] = __float2half(Wl[idx]);
}

// ---------------------------------------------------------------------------
// Fused agg init: a0 = a1 = x_target
// ---------------------------------------------------------------------------
__global__ __launch_bounds__(256) void init_agg(
    const float* __restrict__ x, float* __restrict__ a0, float* __restrict__ a1)
{
    size_t i = (size_t)blockIdx.x * 256 + threadIdx.x;
    if (i >= (size_t)NT * CCH / 4) return;
    float4 v = __ldg((const float4*)x + i);
    ((float4*)a0)[i] = v;
    ((float4*)a1)[i] = v;
}

// ---------------------------------------------------------------------------
// mma.sync GEMM, AMODE: 0 = fp32 A, exact hi/lo split (2 MMA)
//                       1 = fp32 A, plain fp16 round   (1 MMA)
//                       2 = fp16 A, direct             (1 MMA)
// Bt pre-rounded fp16 [256, Ktot] K-major.
// Dual-branch batching: blockIdx.x >= xblocks selects 'b' pointer set.
// A2: second A source for k >= 256 (merge, Ktot=512).
// OUTH: C stored fp16; else fp32.
// ---------------------------------------------------------------------------
#define ROWB 80
#define BUF  (128 * ROWB)
#define STAGE (3 * BUF)
#define SMEMT (2 * STAGE)

template <int AMODE, bool OUTH, bool BIAS, bool RELU>
__global__ __launch_bounds__(256, 2) void mma_gemm(
    const void* __restrict__ Aa, const void* __restrict__ Ab,
    const void* __restrict__ A2a, const void* __restrict__ A2b,
    const __half* __restrict__ Ba, const __half* __restrict__ Bb,
    const float* __restrict__ biasa, const float* __restrict__ biasb,
    void* __restrict__ Ca, void* __restrict__ Cb,
    int M, int Ktot, int lda, int xblocks)
{
    extern __shared__ char smem[];
    const uint32_t sb = smem_u32(smem);
    const int tid = threadIdx.x;
    const int wid = tid >> 5;
    const int lane = tid & 31;
    const int warpM = wid >> 2;
    const int warpN = wid & 3;
    int bx = blockIdx.x;
    const bool sec = (bx >= xblocks);
    if (sec) bx -= xblocks;
    const int bm = bx * 128;
    const int bn = blockIdx.y * 128;
    const void* A  = sec ? Ab  : Aa;
    const void* A2 = sec ? A2b : A2a;
    const __half* Bt = sec ? Bb : Ba;
    const float* bias = sec ? biasb : biasa;
    void* C = sec ? Cb : Ca;

    float acc[4][4][4];
#pragma unroll
    for (int i = 0; i < 4; i++)
#pragma unroll
        for (int j = 0; j < 4; j++)
#pragma unroll
            for (int q = 0; q < 4; q++) acc[i][j][q] = 0.0f;

    float4 aReg[4];      // AMODE 0/1
    uint4 ahReg[2];      // AMODE 2
    uint4 bReg[2];

    auto loadG = [&](int c) {
        const int k0 = c << 5;
        const void* Ap = A;
        int kk = k0;
        if (A2 != nullptr && k0 >= 256) { Ap = A2; kk = k0 - 256; }
        if (AMODE == 2) {
            const __half* Ah = (const __half*)Ap;
#pragma unroll
            for (int i = 0; i < 2; i++) {
                int idx = i * 256 + tid;
                int r = idx >> 2, ch = idx & 3;
                int row = bm + r;
                ahReg[i] = (row < M)
                    ? __ldg((const uint4*)(Ah + (size_t)row * lda + kk) + ch)
                    : make_uint4(0, 0, 0, 0);
            }
        } else {
            const float* Af = (const float*)Ap;
#pragma unroll
            for (int i = 0; i < 4; i++) {
                int idx = i * 256 + tid;
                int r = idx >> 3, c4 = idx & 7;
                int row = bm + r;
                aReg[i] = (row < M)
                    ? __ldg((const float4*)(Af + (size_t)row * lda + kk) + c4)
                    : make_float4(0.f, 0.f, 0.f, 0.f);
            }
        }
#pragma unroll
        for (int i = 0; i < 2; i++) {
            int idx = i * 256 + tid;
            int r = idx >> 2, ch = idx & 3;
            size_t g = (size_t)(bn + r) * Ktot + k0 + ch * 8;
            bReg[i] = __ldg((const uint4*)(Bt + g));
        }
    };

    auto storeS = [&](int s) {
        char* st = smem + s * STAGE;
        if (AMODE == 2) {
#pragma unroll
            for (int i = 0; i < 2; i++) {
                int idx = i * 256 + tid;
                int r = idx >> 2, ch = idx & 3;
                *(uint4*)(st + r * ROWB + ch * 16) = ahReg[i];
            }
        } else {
#pragma unroll
            for (int i = 0; i < 4; i++) {
                int idx = i * 256 + tid;
                int r = idx >> 3, c4 = idx & 7;
                uint32_t off = (uint32_t)(r * ROWB + c4 * 8);
                float4 v = aReg[i];
                __half h0 = __float2half(v.x);
                __half h1 = __float2half(v.y);
                __half h2 = __float2half(v.z);
                __half h3 = __float2half(v.w);
                uint2 ph;
                ph.x = pack2h(h0, h1);
                ph.y = pack2h(h2, h3);
                *(uint2*)(st + off) = ph;
                if (AMODE == 0) {
                    uint2 pl;
                    pl.x = pack2h(__float2half(v.x - __half2float(h0)),
                                  __float2half(v.y - __half2float(h1)));
                    pl.y = pack2h(__float2half(v.z - __half2float(h2)),
                                  __float2half(v.w - __half2float(h3)));
                    *(uint2*)(st + BUF + off) = pl;
                }
            }
        }
#pragma unroll
        for (int i = 0; i < 2; i++) {
            int idx = i * 256 + tid;
            int r = idx >> 2, ch = idx & 3;
            *(uint4*)(st + 2 * BUF + r * ROWB + ch * 16) = bReg[i];
        }
    };

    auto mmaS = [&](int s) {
        const uint32_t base = sb + s * STAGE;
#pragma unroll
        for (int ks = 0; ks < 2; ks++) {
            uint32_t bf[4][2];
#pragma unroll
            for (int ntp = 0; ntp < 2; ntp++) {
                int rB = warpN * 32 + ntp * 16 + ((lane >> 4) & 1) * 8 + (lane & 7);
                int cB = ks * 2 + ((lane >> 3) & 1);
                uint32_t addr = base + 2 * BUF + rB * ROWB + cB * 16;
                uint32_t q[4];
                ldsm4(q, addr);
                bf[ntp * 2][0] = q[0]; bf[ntp * 2][1] = q[1];
                bf[ntp * 2 + 1][0] = q[2]; bf[ntp * 2 + 1][1] = q[3];
            }
#pragma unroll
            for (int mt = 0; mt < 4; mt++) {
                int rA = warpM * 64 + mt * 16 + (lane & 15);
                int cA = ks * 2 + (lane >> 4);
                uint32_t addr = base + rA * ROWB + cA * 16;
                uint32_t ah[4];
                ldsm4(ah, addr);
#pragma unroll
                for (int nt = 0; nt < 4; nt++)
                    mma16816(acc[mt][nt], ah, bf[nt]);
                if (AMODE == 0) {
                    uint32_t al[4];
                    ldsm4(al, addr + BUF);
#pragma unroll
                    for (int nt = 0; nt < 4; nt++)
                        mma16816(acc[mt][nt], al, bf[nt]);
                }
            }
        }
    };

    const int nch = Ktot >> 5;
    loadG(0);
    storeS(0);
    __syncthreads();
    for (int c = 0; c < nch; c++) {
        if (c + 1 < nch) loadG(c + 1);
        mmaS(c & 1);
        if (c + 1 < nch) storeS((c + 1) & 1);
        __syncthreads();
    }

    // Epilogue
#pragma unroll
    for (int mt = 0; mt < 4; mt++) {
        int row0 = bm + warpM * 64 + mt * 16 + (lane >> 2);
#pragma unroll
        for (int nt = 0; nt < 4; nt++) {
            int col = bn + warpN * 32 + nt * 8 + (lane & 3) * 2;
            float bx2 = 0.f, by2 = 0.f;
            if (BIAS) { bx2 = __ldg(bias + col); by2 = __ldg(bias + col + 1); }
            float2 v0 = make_float2(acc[mt][nt][0] + bx2, acc[mt][nt][1] + by2);
            float2 v1 = make_float2(acc[mt][nt][2] + bx2, acc[mt][nt][3] + by2);
            if (RELU) {
                v0.x = fmaxf(v0.x, 0.f); v0.y = fmaxf(v0.y, 0.f);
                v1.x = fmaxf(v1.x, 0.f); v1.y = fmaxf(v1.y, 0.f);
            }
            if (OUTH) {
                __half* Ch = (__half*)C;
                if (row0 < M)
                    *(uint32_t*)(Ch + (size_t)row0 * 256 + col) =
                        pack2h(__float2half(v0.x), __float2half(v0.y));
                if (row0 + 8 < M)
                    *(uint32_t*)(Ch + (size_t)(row0 + 8) * 256 + col) =
                        pack2h(__float2half(v1.x), __float2half(v1.y));
            } else {
                float* Cf = (float*)C;
                if (row0 < M)     *(float2*)(Cf + (size_t)row0 * 256 + col) = v0;
                if (row0 + 8 < M) *(float2*)(Cf + (size_t)(row0 + 8) * 256 + col) = v1;
            }
        }
    }
}

// ---------------------------------------------------------------------------
// Combined edge scatter (both branches, one launch):
// agg[rows[e]] += vals[e] * support_fp16[cols[e]]  (256 ch, 64 thr/edge)
// ---------------------------------------------------------------------------
__global__ __launch_bounds__(256) void scatter_kernel(
    const __half* __restrict__ sup0, const __half* __restrict__ sup1,
    const float* __restrict__ v0, const float* __restrict__ v1,
    const int* __restrict__ r0, const int* __restrict__ r1,
    const int* __restrict__ c0, const int* __restrict__ c1,
    float* __restrict__ a0, float* __restrict__ a1)
{
    long long idx = (long long)blockIdx.x * blockDim.x + threadIdx.x;
    const long long half = (long long)NE * 64;
    if (idx >= 2 * half) return;
    const bool b1 = (idx >= half);
    if (b1) idx -= half;
    const __half* sup = b1 ? sup1 : sup0;
    const float* vals = b1 ? v1 : v0;
    const int* rows = b1 ? r1 : r0;
    const int* cols = b1 ? c1 : c0;
    float* agg = b1 ? a1 : a0;

    int e = (int)(idx >> 6);
    int q = (int)(idx & 63);
    int r = __ldg(rows + e);
    int c = __ldg(cols + e);
    float v = __ldg(vals + e);
    uint2 s = __ldg((const uint2*)(sup + (size_t)c * CCH) + q);
    float2 f01 = __half22float2(*(const __half2*)&s.x);
    float2 f23 = __half22float2(*(const __half2*)&s.y);
    float* dst = agg + (size_t)r * CCH + q * 4;
    asm volatile("red.global.add.v4.f32 [%0], {%1, %2, %3, %4};"
                 :: "l"(dst), "f"(v * f01.x), "f"(v * f01.y),
                    "f"(v * f23.x), "f"(v * f23.y)
                 : "memory");
}

// ---------------------------------------------------------------------------
extern "C" void kernel_launch(void* const* d_in, const int* in_sizes, int n_in,
                              void* d_out, int out_size)
{
    const float* x_t  = (const float*)d_in[0];
    const float* xs0  = (const float*)d_in[1];
    const float* xs1  = (const float*)d_in[2];
    const float* v0   = (const float*)d_in[3];
    const float* v1   = (const float*)d_in[4];
    const int*   r0   = (const int*)d_in[5];
    const int*   c0   = (const int*)d_in[6];
    const int*   r1   = (const int*)d_in[7];
    const int*   c1   = (const int*)d_in[8];
    const float* W0   = (const float*)d_in[9];
    const float* W1   = (const float*)d_in[10];
    const float* mW0  = (const float*)d_in[11];
    const float* mb0  = (const float*)d_in[12];
    const float* mW1  = (const float*)d_in[13];
    const float* mb1  = (const float*)d_in[14];
    const float* Wm   = (const float*)d_in[15];
    const float* bmv  = (const float*)d_in[16];
    float* out = (float*)d_out;

    float *sup0f, *sup1f, *a0, *b0, *a1, *b1;
    __half *wt0, *wt1, *mwt0, *mwt1, *wmt;
    cudaGetSymbolAddress((void**)&sup0f, g_sup0);
    cudaGetSymbolAddress((void**)&sup1f, g_sup1);
    cudaGetSymbolAddress((void**)&a0, g_a0);
    cudaGetSymbolAddress((void**)&b0, g_b0);
    cudaGetSymbolAddress((void**)&a1, g_a1);
    cudaGetSymbolAddress((void**)&b1, g_b1);
    cudaGetSymbolAddress((void**)&wt0, g_wt0);
    cudaGetSymbolAddress((void**)&wt1, g_wt1);
    cudaGetSymbolAddress((void**)&mwt0, g_mwt0);
    cudaGetSymbolAddress((void**)&mwt1, g_mwt1);
    cudaGetSymbolAddress((void**)&wmt, g_wmt);

    __half* sup0 = (__half*)sup0f;
    __half* sup1 = (__half*)sup1f;
    __half* h0 = (__half*)b0;   // fp16 L1/L3 outputs
    __half* h1 = (__half*)b1;
    __half* q0 = (__half*)a0;   // fp16 L2 outputs (agg fp32 dead after L1)
    __half* q1 = (__half*)a1;

    cudaFuncSetAttribute(mma_gemm<1, true, false, false>,
                         cudaFuncAttributeMaxDynamicSharedMemorySize, SMEMT);
    cudaFuncSetAttribute(mma_gemm<1, true, true, true>,
                         cudaFuncAttributeMaxDynamicSharedMemorySize, SMEMT);
    cudaFuncSetAttribute(mma_gemm<2, true, true, true>,
                         cudaFuncAttributeMaxDynamicSharedMemorySize, SMEMT);
    cudaFuncSetAttribute(mma_gemm<2, false, true, false>,
                         cudaFuncAttributeMaxDynamicSharedMemorySize, SMEMT);

    // ---- Weight prep ----
    dim3 gp1((128 * 256 + 255) / 256, 1);
    prep_w<<<gp1, 256>>>(W0, wt0, 128);
    prep_w<<<gp1, 256>>>(W1, wt1, 128);
    dim3 gp3((256 * 256 + 255) / 256, 3);
    prep_w<<<gp3, 256>>>(mW0, mwt0, 256);
    prep_w<<<gp3, 256>>>(mW1, mwt1, 256);
    dim3 gpm((512 * 256 + 255) / 256, 1);
    prep_w<<<gpm, 256>>>(Wm, wmt, 512);

    dim3 blk(256);
    const int xS = (NS + 127) / 128;   // 782
    const int xT = (NT + 127) / 128;   // 391
    dim3 gS(2 * xS, 2);
    dim3 gT(2 * xT, 2);
    dim3 gM(xT, 2);

    // support = fp16(x_src) @ W  (1 MMA, fp16 out, both branches)
    mma_gemm<1, true, false, false><<<gS, blk, SMEMT>>>(
        xs0, xs1, nullptr, nullptr, wt0, wt1, nullptr, nullptr,
        sup0, sup1, NS, 128, 128, xS);

    // agg init = x_target (epsilon = 0)
    init_agg<<<(int)(((size_t)NT * CCH / 4 + 255) / 256), blk>>>(x_t, a0, a1);

    // combined sparse scatter-add
    long long tot = 2LL * NE * 64;
    scatter_kernel<<<(int)((tot + 255) / 256), blk>>>(
        sup0, sup1, v0, v1, r0, r1, c0, c1, a0, a1);

    // MLP L1: fp32 agg -> fp16 h   (1 MMA)
    mma_gemm<1, true, true, true><<<gT, blk, SMEMT>>>(
        a0, a1, nullptr, nullptr, mwt0, mwt1, mb0, mb1,
        h0, h1, NT, 256, 256, xT);
    // MLP L2: fp16 h -> fp16 q     (1 MMA, copy-only A path)
    mma_gemm<2, true, true, true><<<gT, blk, SMEMT>>>(
        h0, h1, nullptr, nullptr, mwt0 + 65536, mwt1 + 65536,
        mb0 + 256, mb1 + 256, q0, q1, NT, 256, 256, xT);
    // MLP L3: fp16 q -> fp16 h
    mma_gemm<2, true, true, true><<<gT, blk, SMEMT>>>(
        q0, q1, nullptr, nullptr, mwt0 + 2 * 65536, mwt1 + 2 * 65536,
        mb0 + 512, mb1 + 512, h0, h1, NT, 256, 256, xT);

    // merge: out = [h0, h1] @ Wm + bm  (fp16 A, K=512)
    mma_gemm<2, false, true, false><<<gM, blk, SMEMT>>>(
        h0, nullptr, h1, nullptr, wmt, nullptr, bmv, nullptr,
        out, nullptr, NT, 512, 256, xT);
}

// round 14
// speedup vs baseline: 2.4362x; 1.3740x over previous
#include <cuda_runtime.h>
#include <cuda_fp16.h>
#include <cstdint>

// Problem constants
#define NT 50000
#define NS 100000
#define NE 400000
#define CIN 128
#define CCH 256
#define NROWS (2 * NT)            /* both branches concatenated */

// ---------------------------------------------------------------------------
// Scratch (device globals — no allocation allowed)
// ---------------------------------------------------------------------------
__device__ float g_sup0[(size_t)NS * CCH];   // aliased fp16 support
__device__ float g_sup1[(size_t)NS * CCH];
__device__ float g_a0[(size_t)NT * CCH];     // fp16 agg, then fp16 L2 out
__device__ float g_b0[(size_t)NT * CCH];     // fp16 L1/L3 out
__device__ float g_a1[(size_t)NT * CCH];
__device__ float g_b1[(size_t)NT * CCH];
// fp16 transposed weights: [N=256, K] K-major
__device__ __half g_wt0[256 * 128];
__device__ __half g_wt1[256 * 128];
__device__ __half g_mwt0[3 * 256 * 256];
__device__ __half g_mwt1[3 * 256 * 256];
__device__ __half g_wmt[256 * 512];
// CSR scratch
__device__ int   g_cnt[NROWS];
__device__ int   g_off[NROWS + 1];
__device__ int   g_bsum[512];
__device__ int   g_ecol[2 * NE];
__device__ float g_eval[2 * NE];

// ---------------------------------------------------------------------------
// Helpers
// ---------------------------------------------------------------------------
__device__ __forceinline__ uint32_t smem_u32(const void* p) {
    uint32_t a;
    asm("{ .reg .u64 t; cvta.to.shared.u64 t, %1; cvt.u32.u64 %0, t; }"
        : "=r"(a) : "l"(p));
    return a;
}

__device__ __forceinline__ void ldsm4(uint32_t* r, uint32_t addr) {
    asm volatile("ldmatrix.sync.aligned.m8n8.x4.shared.b16 {%0,%1,%2,%3}, [%4];"
                 : "=r"(r[0]), "=r"(r[1]), "=r"(r[2]), "=r"(r[3]) : "r"(addr));
}

__device__ __forceinline__ void mma16816(float* d, const uint32_t* a, const uint32_t* b) {
    asm volatile(
        "mma.sync.aligned.m16n8k16.row.col.f32.f16.f16.f32 "
        "{%0,%1,%2,%3}, {%4,%5,%6,%7}, {%8,%9}, {%0,%1,%2,%3};"
        : "+f"(d[0]), "+f"(d[1]), "+f"(d[2]), "+f"(d[3])
        : "r"(a[0]), "r"(a[1]), "r"(a[2]), "r"(a[3]), "r"(b[0]), "r"(b[1]));
}

__device__ __forceinline__ uint32_t pack2h(__half x, __half y) {
    return ((uint32_t)__half_as_ushort(y) << 16) | __half_as_ushort(x);
}

// ---------------------------------------------------------------------------
// Weight prep: W [K, 256] fp32 -> Wt [256, K] fp16 (K-major)
// ---------------------------------------------------------------------------
__global__ __launch_bounds__(256) void prep_w(
    const float* __restrict__ W, __half* __restrict__ Wt, int K)
{
    int l = blockIdx.y;
    const float* Wl = W + (size_t)l * K * 256;
    __half* Wtl = Wt + (size_t)l * K * 256;
    int idx = blockIdx.x * 256 + threadIdx.x;
    if (idx >= K * 256) return;
    int k = idx >> 8;
    int n = idx & 255;
    Wtl[(size_t)n * K + k] = __float2half(Wl[idx]);
}

// ---------------------------------------------------------------------------
// CSR build: histogram -> 3-kernel exclusive scan -> permuted fill
// ---------------------------------------------------------------------------
__global__ __launch_bounds__(256) void k_hist(
    const int* __restrict__ r0, const int* __restrict__ r1, int* __restrict__ cnt)
{
    int idx = blockIdx.x * 256 + threadIdx.x;
    if (idx >= 2 * NE) return;
    int g = (idx < NE) ? __ldg(r0 + idx) : (NT + __ldg(r1 + idx - NE));
    atomicAdd(cnt + g, 1);
}

__global__ __launch_bounds__(256) void k_bsum(
    const int* __restrict__ cnt, int* __restrict__ bsum)
{
    __shared__ int sm[256];
    int g = blockIdx.x * 256 + threadIdx.x;
    sm[threadIdx.x] = (g < NROWS) ? cnt[g] : 0;
    __syncthreads();
    for (int s = 128; s > 0; s >>= 1) {
        if (threadIdx.x < s) sm[threadIdx.x] += sm[threadIdx.x + s];
        __syncthreads();
    }
    if (threadIdx.x == 0) bsum[blockIdx.x] = sm[0];
}

__global__ __launch_bounds__(512) void k_bscan(int* __restrict__ bsum, int nblk)
{
    __shared__ int sm[512];
    int t = threadIdx.x;
    int own = (t < nblk) ? bsum[t] : 0;
    sm[t] = own;
    __syncthreads();
    for (int s = 1; s < 512; s <<= 1) {
        int add = (t >= s) ? sm[t - s] : 0;
        __syncthreads();
        sm[t] += add;
        __syncthreads();
    }
    if (t < nblk) bsum[t] = sm[t] - own;   // exclusive
}

__global__ __launch_bounds__(256) void k_off(
    const int* __restrict__ cnt, const int* __restrict__ bsum, int* __restrict__ off)
{
    __shared__ int sm[256];
    int g = blockIdx.x * 256 + threadIdx.x;
    int own = (g < NROWS) ? cnt[g] : 0;
    sm[threadIdx.x] = own;
    __syncthreads();
    for (int s = 1; s < 256; s <<= 1) {
        int add = (threadIdx.x >= (unsigned)s) ? sm[threadIdx.x - s] : 0;
        __syncthreads();
        sm[threadIdx.x] += add;
        __syncthreads();
    }
    if (g < NROWS) off[g] = sm[threadIdx.x] - own + bsum[blockIdx.x];
    if (g == 0) off[NROWS] = 2 * NE;
}

__global__ __launch_bounds__(256) void k_fill(
    const int* __restrict__ r0, const int* __restrict__ r1,
    const int* __restrict__ c0, const int* __restrict__ c1,
    const float* __restrict__ v0, const float* __restrict__ v1,
    const int* __restrict__ off, int* __restrict__ cur,
    int* __restrict__ ecol, float* __restrict__ eval)
{
    int idx = blockIdx.x * 256 + threadIdx.x;
    if (idx >= 2 * NE) return;
    int g, c; float v;
    if (idx < NE) {
        g = __ldg(r0 + idx); c = __ldg(c0 + idx); v = __ldg(v0 + idx);
    } else {
        int e = idx - NE;
        g = NT + __ldg(r1 + e); c = __ldg(c1 + e); v = __ldg(v1 + e);
    }
    int pos = __ldg(off + g) + atomicAdd(cur + g, 1);
    ecol[pos] = c;
    eval[pos] = v;
}

// ---------------------------------------------------------------------------
// CSR aggregate: one warp per target row. 8 ch/lane (uint4 fp16 gather).
// agg_fp16[row] = fp16( x_target[row] + sum_e val_e * sup[col_e] )
// ---------------------------------------------------------------------------
__global__ __launch_bounds__(256) void k_agg(
    const float* __restrict__ x_t,
    const __half* __restrict__ sup0, const __half* __restrict__ sup1,
    const int* __restrict__ off,
    const int* __restrict__ ecol, const float* __restrict__ eval,
    __half* __restrict__ agg0, __half* __restrict__ agg1)
{
    int t = blockIdx.x * 8 + (threadIdx.x >> 5);
    if (t >= NROWS) return;
    const int lane = threadIdx.x & 31;
    const bool br = (t >= NT);
    const int row = br ? t - NT : t;
    const __half* sup = br ? sup1 : sup0;
    __half* agg = br ? agg1 : agg0;

    float acc[8];
    {
        const float4* xp = (const float4*)(x_t + (size_t)row * CCH + lane * 8);
        float4 x0 = __ldg(xp), x1 = __ldg(xp + 1);
        acc[0] = x0.x; acc[1] = x0.y; acc[2] = x0.z; acc[3] = x0.w;
        acc[4] = x1.x; acc[5] = x1.y; acc[6] = x1.z; acc[7] = x1.w;
    }
    int i0 = __ldg(off + t), i1 = __ldg(off + t + 1);
    for (int i = i0; i < i1; i++) {
        int c = __ldg(ecol + i);
        float v = __ldg(eval + i);
        uint4 s = __ldg((const uint4*)(sup + (size_t)c * CCH + lane * 8));
        float2 f0 = __half22float2(*(const __half2*)&s.x);
        float2 f1 = __half22float2(*(const __half2*)&s.y);
        float2 f2 = __half22float2(*(const __half2*)&s.z);
        float2 f3 = __half22float2(*(const __half2*)&s.w);
        acc[0] = fmaf(v, f0.x, acc[0]); acc[1] = fmaf(v, f0.y, acc[1]);
        acc[2] = fmaf(v, f1.x, acc[2]); acc[3] = fmaf(v, f1.y, acc[3]);
        acc[4] = fmaf(v, f2.x, acc[4]); acc[5] = fmaf(v, f2.y, acc[5]);
        acc[6] = fmaf(v, f3.x, acc[6]); acc[7] = fmaf(v, f3.y, acc[7]);
    }
    uint4 o;
    o.x = pack2h(__float2half(acc[0]), __float2half(acc[1]));
    o.y = pack2h(__float2half(acc[2]), __float2half(acc[3]));
    o.z = pack2h(__float2half(acc[4]), __float2half(acc[5]));
    o.w = pack2h(__float2half(acc[6]), __float2half(acc[7]));
    *(uint4*)(agg + (size_t)row * CCH + lane * 8) = o;
}

// ---------------------------------------------------------------------------
// mma.sync GEMM, AMODE: 1 = fp32 A, fp16 round (1 MMA); 2 = fp16 A direct.
// Bt pre-rounded fp16 [256, Ktot] K-major. Dual-branch via blockIdx.x.
// A2: second A source for k >= 256 (merge, Ktot=512). OUTH: fp16 C.
// ---------------------------------------------------------------------------
#define ROWB 80
#define BUF  (128 * ROWB)
#define STAGE (3 * BUF)
#define SMEMT (2 * STAGE)

template <int AMODE, bool OUTH, bool BIAS, bool RELU>
__global__ __launch_bounds__(256, 2) void mma_gemm(
    const void* __restrict__ Aa, const void* __restrict__ Ab,
    const void* __restrict__ A2a, const void* __restrict__ A2b,
    const __half* __restrict__ Ba, const __half* __restrict__ Bb,
    const float* __restrict__ biasa, const float* __restrict__ biasb,
    void* __restrict__ Ca, void* __restrict__ Cb,
    int M, int Ktot, int lda, int xblocks)
{
    extern __shared__ char smem[];
    const uint32_t sb = smem_u32(smem);
    const int tid = threadIdx.x;
    const int wid = tid >> 5;
    const int lane = tid & 31;
    const int warpM = wid >> 2;
    const int warpN = wid & 3;
    int bx = blockIdx.x;
    const bool sec = (bx >= xblocks);
    if (sec) bx -= xblocks;
    const int bm = bx * 128;
    const int bn = blockIdx.y * 128;
    const void* A  = sec ? Ab  : Aa;
    const void* A2 = sec ? A2b : A2a;
    const __half* Bt = sec ? Bb : Ba;
    const float* bias = sec ? biasb : biasa;
    void* C = sec ? Cb : Ca;

    float acc[4][4][4];
#pragma unroll
    for (int i = 0; i < 4; i++)
#pragma unroll
        for (int j = 0; j < 4; j++)
#pragma unroll
            for (int q = 0; q < 4; q++) acc[i][j][q] = 0.0f;

    float4 aReg[4];
    uint4 ahReg[2];
    uint4 bReg[2];

    auto loadG = [&](int c) {
        const int k0 = c << 5;
        const void* Ap = A;
        int kk = k0;
        if (A2 != nullptr && k0 >= 256) { Ap = A2; kk = k0 - 256; }
        if (AMODE == 2) {
            const __half* Ah = (const __half*)Ap;
#pragma unroll
            for (int i = 0; i < 2; i++) {
                int idx = i * 256 + tid;
                int r = idx >> 2, ch = idx & 3;
                int row = bm + r;
                ahReg[i] = (row < M)
                    ? __ldg((const uint4*)(Ah + (size_t)row * lda + kk) + ch)
                    : make_uint4(0, 0, 0, 0);
            }
        } else {
            const float* Af = (const float*)Ap;
#pragma unroll
            for (int i = 0; i < 4; i++) {
                int idx = i * 256 + tid;
                int r = idx >> 3, c4 = idx & 7;
                int row = bm + r;
                aReg[i] = (row < M)
                    ? __ldg((const float4*)(Af + (size_t)row * lda + kk) + c4)
                    : make_float4(0.f, 0.f, 0.f, 0.f);
            }
        }
#pragma unroll
        for (int i = 0; i < 2; i++) {
            int idx = i * 256 + tid;
            int r = idx >> 2, ch = idx & 3;
            size_t g = (size_t)(bn + r) * Ktot + k0 + ch * 8;
            bReg[i] = __ldg((const uint4*)(Bt + g));
        }
    };

    auto storeS = [&](int s) {
        char* st = smem + s * STAGE;
        if (AMODE == 2) {
#pragma unroll
            for (int i = 0; i < 2; i++) {
                int idx = i * 256 + tid;
                int r = idx >> 2, ch = idx & 3;
                *(uint4*)(st + r * ROWB + ch * 16) = ahReg[i];
            }
        } else {
#pragma unroll
            for (int i = 0; i < 4; i++) {
                int idx = i * 256 + tid;
                int r = idx >> 3, c4 = idx & 7;
                uint32_t off = (uint32_t)(r * ROWB + c4 * 8);
                float4 v = aReg[i];
                uint2 ph;
                ph.x = pack2h(__float2half(v.x), __float2half(v.y));
                ph.y = pack2h(__float2half(v.z), __float2half(v.w));
                *(uint2*)(st + off) = ph;
            }
        }
#pragma unroll
        for (int i = 0; i < 2; i++) {
            int idx = i * 256 + tid;
            int r = idx >> 2, ch = idx & 3;
            *(uint4*)(st + 2 * BUF + r * ROWB + ch * 16) = bReg[i];
        }
    };

    auto mmaS = [&](int s) {
        const uint32_t base = sb + s * STAGE;
#pragma unroll
        for (int ks = 0; ks < 2; ks++) {
            uint32_t bf[4][2];
#pragma unroll
            for (int ntp = 0; ntp < 2; ntp++) {
                int rB = warpN * 32 + ntp * 16 + ((lane >> 4) & 1) * 8 + (lane & 7);
                int cB = ks * 2 + ((lane >> 3) & 1);
                uint32_t addr = base + 2 * BUF + rB * ROWB + cB * 16;
                uint32_t q[4];
                ldsm4(q, addr);
                bf[ntp * 2][0] = q[0]; bf[ntp * 2][1] = q[1];
                bf[ntp * 2 + 1][0] = q[2]; bf[ntp * 2 + 1][1] = q[3];
            }
#pragma unroll
            for (int mt = 0; mt < 4; mt++) {
                int rA = warpM * 64 + mt * 16 + (lane & 15);
                int cA = ks * 2 + (lane >> 4);
                uint32_t addr = base + rA * ROWB + cA * 16;
                uint32_t ah[4];
                ldsm4(ah, addr);
#pragma unroll
                for (int nt = 0; nt < 4; nt++)
                    mma16816(acc[mt][nt], ah, bf[nt]);
            }
        }
    };

    const int nch = Ktot >> 5;
    loadG(0);
    storeS(0);
    __syncthreads();
    for (int c = 0; c < nch; c++) {
        if (c + 1 < nch) loadG(c + 1);
        mmaS(c & 1);
        if (c + 1 < nch) storeS((c + 1) & 1);
        __syncthreads();
    }

    // Epilogue
#pragma unroll
    for (int mt = 0; mt < 4; mt++) {
        int row0 = bm + warpM * 64 + mt * 16 + (lane >> 2);
#pragma unroll
        for (int nt = 0; nt < 4; nt++) {
            int col = bn + warpN * 32 + nt * 8 + (lane & 3) * 2;
            float bx2 = 0.f, by2 = 0.f;
            if (BIAS) { bx2 = __ldg(bias + col); by2 = __ldg(bias + col + 1); }
            float2 v0 = make_float2(acc[mt][nt][0] + bx2, acc[mt][nt][1] + by2);
            float2 v1 = make_float2(acc[mt][nt][2] + bx2, acc[mt][nt][3] + by2);
            if (RELU) {
                v0.x = fmaxf(v0.x, 0.f); v0.y = fmaxf(v0.y, 0.f);
                v1.x = fmaxf(v1.x, 0.f); v1.y = fmaxf(v1.y, 0.f);
            }
            if (OUTH) {
                __half* Ch = (__half*)C;
                if (row0 < M)
                    *(uint32_t*)(Ch + (size_t)row0 * 256 + col) =
                        pack2h(__float2half(v0.x), __float2half(v0.y));
                if (row0 + 8 < M)
                    *(uint32_t*)(Ch + (size_t)(row0 + 8) * 256 + col) =
                        pack2h(__float2half(v1.x), __float2half(v1.y));
            } else {
                float* Cf = (float*)C;
                if (row0 < M)     *(float2*)(Cf + (size_t)row0 * 256 + col) = v0;
                if (row0 + 8 < M) *(float2*)(Cf + (size_t)(row0 + 8) * 256 + col) = v1;
            }
        }
    }
}

// ---------------------------------------------------------------------------
extern "C" void kernel_launch(void* const* d_in, const int* in_sizes, int n_in,
                              void* d_out, int out_size)
{
    const float* x_t  = (const float*)d_in[0];
    const float* xs0  = (const float*)d_in[1];
    const float* xs1  = (const float*)d_in[2];
    const float* v0   = (const float*)d_in[3];
    const float* v1   = (const float*)d_in[4];
    const int*   r0   = (const int*)d_in[5];
    const int*   c0   = (const int*)d_in[6];
    const int*   r1   = (const int*)d_in[7];
    const int*   c1   = (const int*)d_in[8];
    const float* W0   = (const float*)d_in[9];
    const float* W1   = (const float*)d_in[10];
    const float* mW0  = (const float*)d_in[11];
    const float* mb0  = (const float*)d_in[12];
    const float* mW1  = (const float*)d_in[13];
    const float* mb1  = (const float*)d_in[14];
    const float* Wm   = (const float*)d_in[15];
    const float* bmv  = (const float*)d_in[16];
    float* out = (float*)d_out;

    float *sup0f, *sup1f, *a0, *b0, *a1, *b1;
    __half *wt0, *wt1, *mwt0, *mwt1, *wmt;
    int *cnt, *off, *bsum, *ecol;
    float *eval;
    cudaGetSymbolAddress((void**)&sup0f, g_sup0);
    cudaGetSymbolAddress((void**)&sup1f, g_sup1);
    cudaGetSymbolAddress((void**)&a0, g_a0);
    cudaGetSymbolAddress((void**)&b0, g_b0);
    cudaGetSymbolAddress((void**)&a1, g_a1);
    cudaGetSymbolAddress((void**)&b1, g_b1);
    cudaGetSymbolAddress((void**)&wt0, g_wt0);
    cudaGetSymbolAddress((void**)&wt1, g_wt1);
    cudaGetSymbolAddress((void**)&mwt0, g_mwt0);
    cudaGetSymbolAddress((void**)&mwt1, g_mwt1);
    cudaGetSymbolAddress((void**)&wmt, g_wmt);
    cudaGetSymbolAddress((void**)&cnt, g_cnt);
    cudaGetSymbolAddress((void**)&off, g_off);
    cudaGetSymbolAddress((void**)&bsum, g_bsum);
    cudaGetSymbolAddress((void**)&ecol, g_ecol);
    cudaGetSymbolAddress((void**)&eval, g_eval);

    __half* sup0 = (__half*)sup0f;
    __half* sup1 = (__half*)sup1f;
    __half* agg0 = (__half*)a0;   // fp16 agg (L1 input)
    __half* agg1 = (__half*)a1;
    __half* h0 = (__half*)b0;     // fp16 L1/L3 outputs
    __half* h1 = (__half*)b1;
    __half* q0 = (__half*)a0;     // fp16 L2 outputs (agg dead after L1)
    __half* q1 = (__half*)a1;

    cudaFuncSetAttribute(mma_gemm<1, true, false, false>,
                         cudaFuncAttributeMaxDynamicSharedMemorySize, SMEMT);
    cudaFuncSetAttribute(mma_gemm<2, true, true, true>,
                         cudaFuncAttributeMaxDynamicSharedMemorySize, SMEMT);
    cudaFuncSetAttribute(mma_gemm<2, false, true, false>,
                         cudaFuncAttributeMaxDynamicSharedMemorySize, SMEMT);

    // ---- Weight prep ----
    dim3 gp1((128 * 256 + 255) / 256, 1);
    prep_w<<<gp1, 256>>>(W0, wt0, 128);
    prep_w<<<gp1, 256>>>(W1, wt1, 128);
    dim3 gp3((256 * 256 + 255) / 256, 3);
    prep_w<<<gp3, 256>>>(mW0, mwt0, 256);
    prep_w<<<gp3, 256>>>(mW1, mwt1, 256);
    dim3 gpm((512 * 256 + 255) / 256, 1);
    prep_w<<<gpm, 256>>>(Wm, wmt, 512);

    // ---- CSR build (overlaps support GEMM in issue order) ----
    const int nblk = (NROWS + 255) / 256;   // 391
    cudaMemsetAsync(cnt, 0, NROWS * sizeof(int));
    k_hist<<<(2 * NE + 255) / 256, 256>>>(r0, r1, cnt);
    k_bsum<<<nblk, 256>>>(cnt, bsum);
    k_bscan<<<1, 512>>>(bsum, nblk);
    k_off<<<nblk, 256>>>(cnt, bsum, off);
    cudaMemsetAsync(cnt, 0, NROWS * sizeof(int));
    k_fill<<<(2 * NE + 255) / 256, 256>>>(r0, r1, c0, c1, v0, v1,
                                          off, cnt, ecol, eval);

    dim3 blk(256);
    const int xS = (NS + 127) / 128;   // 782
    const int xT = (NT + 127) / 128;   // 391
    dim3 gS(2 * xS, 2);
    dim3 gT(2 * xT, 2);
    dim3 gM(xT, 2);

    // support = fp16(x_src) @ W  (1 MMA, fp16 out, both branches)
    mma_gemm<1, true, false, false><<<gS, blk, SMEMT>>>(
        xs0, xs1, nullptr, nullptr, wt0, wt1, nullptr, nullptr,
        sup0, sup1, NS, 128, 128, xS);

    // CSR aggregate: agg = fp16(x_t + A @ sup)   (no atomics)
    k_agg<<<(NROWS + 7) / 8, 256>>>(x_t, sup0, sup1, off, ecol, eval,
                                    agg0, agg1);

    // MLP L1: fp16 agg -> fp16 h  (copy-only A path)
    mma_gemm<2, true, true, true><<<gT, blk, SMEMT>>>(
        agg0, agg1, nullptr, nullptr, mwt0, mwt1, mb0, mb1,
        h0, h1, NT, 256, 256, xT);
    // MLP L2: fp16 h -> fp16 q
    mma_gemm<2, true, true, true><<<gT, blk, SMEMT>>>(
        h0, h1, nullptr, nullptr, mwt0 + 65536, mwt1 + 65536,
        mb0 + 256, mb1 + 256, q0, q1, NT, 256, 256, xT);
    // MLP L3: fp16 q -> fp16 h
    mma_gemm<2, true, true, true><<<gT, blk, SMEMT>>>(
        q0, q1, nullptr, nullptr, mwt0 + 2 * 65536, mwt1 + 2 * 65536,
        mb0 + 512, mb1 + 512, h0, h1, NT, 256, 256, xT);

    // merge: out = [h0, h1] @ Wm + bm  (fp16 A, K=512)
    mma_gemm<2, false, true, false><<<gM, blk, SMEMT>>>(
        h0, nullptr, h1, nullptr, wmt, nullptr, bmv, nullptr,
        out, nullptr, NT, 512, 256, xT);
}

// round 15
// speedup vs baseline: 2.4942x; 1.0238x over previous
#include <cuda_runtime.h>
#include <cuda_fp16.h>
#include <cstdint>

// Problem constants
#define NT 50000
#define NS 100000
#define NE 400000
#define CIN 128
#define CCH 256
#define NROWS (2 * NT)            /* both branches concatenated */

// ---------------------------------------------------------------------------
// Scratch (device globals — no allocation allowed)
// ---------------------------------------------------------------------------
__device__ float g_sup0[(size_t)NS * CCH];   // aliased fp16 support
__device__ float g_sup1[(size_t)NS * CCH];
__device__ float g_a0[(size_t)NT * CCH];     // fp16 agg, then fp16 L2 out
__device__ float g_b0[(size_t)NT * CCH];     // fp16 L1/L3 out
__device__ float g_a1[(size_t)NT * CCH];
__device__ float g_b1[(size_t)NT * CCH];
// fp16 transposed weights: [N=256, K] K-major
__device__ __half g_wt0[256 * 128];
__device__ __half g_wt1[256 * 128];
__device__ __half g_mwt0[3 * 256 * 256];
__device__ __half g_mwt1[3 * 256 * 256];
__device__ __half g_wmt[256 * 512];
// CSR scratch
__device__ int   g_cnt[NROWS];
__device__ int   g_off[NROWS + 1];
__device__ int   g_bsum[512];
__device__ int   g_ecol[2 * NE];
__device__ float g_eval[2 * NE];

// ---------------------------------------------------------------------------
// Helpers
// ---------------------------------------------------------------------------
__device__ __forceinline__ uint32_t smem_u32(const void* p) {
    uint32_t a;
    asm("{ .reg .u64 t; cvta.to.shared.u64 t, %1; cvt.u32.u64 %0, t; }"
        : "=r"(a) : "l"(p));
    return a;
}

__device__ __forceinline__ void ldsm4(uint32_t* r, uint32_t addr) {
    asm volatile("ldmatrix.sync.aligned.m8n8.x4.shared.b16 {%0,%1,%2,%3}, [%4];"
                 : "=r"(r[0]), "=r"(r[1]), "=r"(r[2]), "=r"(r[3]) : "r"(addr));
}

__device__ __forceinline__ void mma16816(float* d, const uint32_t* a, const uint32_t* b) {
    asm volatile(
        "mma.sync.aligned.m16n8k16.row.col.f32.f16.f16.f32 "
        "{%0,%1,%2,%3}, {%4,%5,%6,%7}, {%8,%9}, {%0,%1,%2,%3};"
        : "+f"(d[0]), "+f"(d[1]), "+f"(d[2]), "+f"(d[3])
        : "r"(a[0]), "r"(a[1]), "r"(a[2]), "r"(a[3]), "r"(b[0]), "r"(b[1]));
}

__device__ __forceinline__ uint32_t pack2h(__half x, __half y) {
    return ((uint32_t)__half_as_ushort(y) << 16) | __half_as_ushort(x);
}

#define CP_ASYNC16(dst, src, sz) \
    asm volatile("cp.async.cg.shared.global [%0], [%1], 16, %2;" \
                 :: "r"(dst), "l"(src), "r"(sz) : "memory")
#define CP_COMMIT() asm volatile("cp.async.commit_group;" ::: "memory")
#define CP_WAIT2()  asm volatile("cp.async.wait_group 2;" ::: "memory")

// ---------------------------------------------------------------------------
// Weight prep: W [K, 256] fp32 -> Wt [256, K] fp16 (K-major)
// ---------------------------------------------------------------------------
__global__ __launch_bounds__(256) void prep_w(
    const float* __restrict__ W, __half* __restrict__ Wt, int K)
{
    int l = blockIdx.y;
    const float* Wl = W + (size_t)l * K * 256;
    __half* Wtl = Wt + (size_t)l * K * 256;
    int idx = blockIdx.x * 256 + threadIdx.x;
    if (idx >= K * 256) return;
    int k = idx >> 8;
    int n = idx & 255;
    Wtl[(size_t)n * K + k] = __float2half(Wl[idx]);
}

// ---------------------------------------------------------------------------
// CSR build: histogram -> 3-kernel exclusive scan -> permuted fill
// ---------------------------------------------------------------------------
__global__ __launch_bounds__(256) void k_hist(
    const int* __restrict__ r0, const int* __restrict__ r1, int* __restrict__ cnt)
{
    int idx = blockIdx.x * 256 + threadIdx.x;
    if (idx >= 2 * NE) return;
    int g = (idx < NE) ? __ldg(r0 + idx) : (NT + __ldg(r1 + idx - NE));
    atomicAdd(cnt + g, 1);
}

__global__ __launch_bounds__(256) void k_bsum(
    const int* __restrict__ cnt, int* __restrict__ bsum)
{
    __shared__ int sm[256];
    int g = blockIdx.x * 256 + threadIdx.x;
    sm[threadIdx.x] = (g < NROWS) ? cnt[g] : 0;
    __syncthreads();
    for (int s = 128; s > 0; s >>= 1) {
        if (threadIdx.x < s) sm[threadIdx.x] += sm[threadIdx.x + s];
        __syncthreads();
    }
    if (threadIdx.x == 0) bsum[blockIdx.x] = sm[0];
}

__global__ __launch_bounds__(512) void k_bscan(int* __restrict__ bsum, int nblk)
{
    __shared__ int sm[512];
    int t = threadIdx.x;
    int own = (t < nblk) ? bsum[t] : 0;
    sm[t] = own;
    __syncthreads();
    for (int s = 1; s < 512; s <<= 1) {
        int add = (t >= s) ? sm[t - s] : 0;
        __syncthreads();
        sm[t] += add;
        __syncthreads();
    }
    if (t < nblk) bsum[t] = sm[t] - own;   // exclusive
}

__global__ __launch_bounds__(256) void k_off(
    const int* __restrict__ cnt, const int* __restrict__ bsum, int* __restrict__ off)
{
    __shared__ int sm[256];
    int g = blockIdx.x * 256 + threadIdx.x;
    int own = (g < NROWS) ? cnt[g] : 0;
    sm[threadIdx.x] = own;
    __syncthreads();
    for (int s = 1; s < 256; s <<= 1) {
        int add = (threadIdx.x >= (unsigned)s) ? sm[threadIdx.x - s] : 0;
        __syncthreads();
        sm[threadIdx.x] += add;
        __syncthreads();
    }
    if (g < NROWS) off[g] = sm[threadIdx.x] - own + bsum[blockIdx.x];
    if (g == 0) off[NROWS] = 2 * NE;
}

__global__ __launch_bounds__(256) void k_fill(
    const int* __restrict__ r0, const int* __restrict__ r1,
    const int* __restrict__ c0, const int* __restrict__ c1,
    const float* __restrict__ v0, const float* __restrict__ v1,
    const int* __restrict__ off, int* __restrict__ cur,
    int* __restrict__ ecol, float* __restrict__ eval)
{
    int idx = blockIdx.x * 256 + threadIdx.x;
    if (idx >= 2 * NE) return;
    int g, c; float v;
    if (idx < NE) {
        g = __ldg(r0 + idx); c = __ldg(c0 + idx); v = __ldg(v0 + idx);
    } else {
        int e = idx - NE;
        g = NT + __ldg(r1 + e); c = __ldg(c1 + e); v = __ldg(v1 + e);
    }
    int pos = __ldg(off + g) + atomicAdd(cur + g, 1);
    ecol[pos] = c;
    eval[pos] = v;
}

// ---------------------------------------------------------------------------
// CSR aggregate: one warp per target row. 8 ch/lane (uint4 fp16 gather).
// agg_fp16[row] = fp16( x_target[row] + sum_e val_e * sup[col_e] )
// ---------------------------------------------------------------------------
__global__ __launch_bounds__(256) void k_agg(
    const float* __restrict__ x_t,
    const __half* __restrict__ sup0, const __half* __restrict__ sup1,
    const int* __restrict__ off,
    const int* __restrict__ ecol, const float* __restrict__ eval,
    __half* __restrict__ agg0, __half* __restrict__ agg1)
{
    int t = blockIdx.x * 8 + (threadIdx.x >> 5);
    if (t >= NROWS) return;
    const int lane = threadIdx.x & 31;
    const bool br = (t >= NT);
    const int row = br ? t - NT : t;
    const __half* sup = br ? sup1 : sup0;
    __half* agg = br ? agg1 : agg0;

    float acc[8];
    {
        const float4* xp = (const float4*)(x_t + (size_t)row * CCH + lane * 8);
        float4 x0 = __ldg(xp), x1 = __ldg(xp + 1);
        acc[0] = x0.x; acc[1] = x0.y; acc[2] = x0.z; acc[3] = x0.w;
        acc[4] = x1.x; acc[5] = x1.y; acc[6] = x1.z; acc[7] = x1.w;
    }
    int i0 = __ldg(off + t), i1 = __ldg(off + t + 1);
    for (int i = i0; i < i1; i++) {
        int c = __ldg(ecol + i);
        float v = __ldg(eval + i);
        uint4 s = __ldg((const uint4*)(sup + (size_t)c * CCH + lane * 8));
        float2 f0 = __half22float2(*(const __half2*)&s.x);
        float2 f1 = __half22float2(*(const __half2*)&s.y);
        float2 f2 = __half22float2(*(const __half2*)&s.z);
        float2 f3 = __half22float2(*(const __half2*)&s.w);
        acc[0] = fmaf(v, f0.x, acc[0]); acc[1] = fmaf(v, f0.y, acc[1]);
        acc[2] = fmaf(v, f1.x, acc[2]); acc[3] = fmaf(v, f1.y, acc[3]);
        acc[4] = fmaf(v, f2.x, acc[4]); acc[5] = fmaf(v, f2.y, acc[5]);
        acc[6] = fmaf(v, f3.x, acc[6]); acc[7] = fmaf(v, f3.y, acc[7]);
    }
    uint4 o;
    o.x = pack2h(__float2half(acc[0]), __float2half(acc[1]));
    o.y = pack2h(__float2half(acc[2]), __float2half(acc[3]));
    o.z = pack2h(__float2half(acc[4]), __float2half(acc[5]));
    o.w = pack2h(__float2half(acc[6]), __float2half(acc[7]));
    *(uint4*)(agg + (size_t)row * CCH + lane * 8) = o;
}

// ---------------------------------------------------------------------------
// mma.sync GEMM.
// AMODE 1: fp32 A, fp16 round in regs (2-stage reg-staged pipeline).
// AMODE 2: fp16 A, 4-stage cp.async pipeline (copy-only, no reg staging).
// Bt pre-rounded fp16 [256, Ktot] K-major. Dual-branch via blockIdx.x.
// A2: second A source for k >= 256 (merge, Ktot=512). OUTH: fp16 C.
// ---------------------------------------------------------------------------
#define ROWB 80
#define BUF  (128 * ROWB)          /* 10240 B */
#define STAGE1 (3 * BUF)           /* AMODE1: AH, (unused), B         */
#define PSTAGE (2 * BUF)           /* AMODE2: A, B = 20480 B          */
#define SMEMT  (4 * PSTAGE)        /* 81920 B (covers both modes)     */

template <int AMODE, bool OUTH, bool BIAS, bool RELU>
__global__ __launch_bounds__(256, 2) void mma_gemm(
    const void* __restrict__ Aa, const void* __restrict__ Ab,
    const void* __restrict__ A2a, const void* __restrict__ A2b,
    const __half* __restrict__ Ba, const __half* __restrict__ Bb,
    const float* __restrict__ biasa, const float* __restrict__ biasb,
    void* __restrict__ Ca, void* __restrict__ Cb,
    int M, int Ktot, int lda, int xblocks)
{
    extern __shared__ char smem[];
    const uint32_t sb = smem_u32(smem);
    const int tid = threadIdx.x;
    const int wid = tid >> 5;
    const int lane = tid & 31;
    const int warpM = wid >> 2;
    const int warpN = wid & 3;
    int bx = blockIdx.x;
    const bool sec = (bx >= xblocks);
    if (sec) bx -= xblocks;
    const int bm = bx * 128;
    const int bn = blockIdx.y * 128;
    const void* A  = sec ? Ab  : Aa;
    const void* A2 = sec ? A2b : A2a;
    const __half* Bt = sec ? Bb : Ba;
    const float* bias = sec ? biasb : biasa;
    void* C = sec ? Cb : Ca;

    float acc[4][4][4];
#pragma unroll
    for (int i = 0; i < 4; i++)
#pragma unroll
        for (int j = 0; j < 4; j++)
#pragma unroll
            for (int q = 0; q < 4; q++) acc[i][j][q] = 0.0f;

    const int nch = Ktot >> 5;

    // MMA over one resident stage; A at base, B at base + bOff.
    auto mmaS = [&](uint32_t base, uint32_t bOff) {
#pragma unroll
        for (int ks = 0; ks < 2; ks++) {
            uint32_t bf[4][2];
#pragma unroll
            for (int ntp = 0; ntp < 2; ntp++) {
                int rB = warpN * 32 + ntp * 16 + ((lane >> 4) & 1) * 8 + (lane & 7);
                int cB = ks * 2 + ((lane >> 3) & 1);
                uint32_t addr = base + bOff + rB * ROWB + cB * 16;
                uint32_t q[4];
                ldsm4(q, addr);
                bf[ntp * 2][0] = q[0]; bf[ntp * 2][1] = q[1];
                bf[ntp * 2 + 1][0] = q[2]; bf[ntp * 2 + 1][1] = q[3];
            }
#pragma unroll
            for (int mt = 0; mt < 4; mt++) {
                int rA = warpM * 64 + mt * 16 + (lane & 15);
                int cA = ks * 2 + (lane >> 4);
                uint32_t addr = base + rA * ROWB + cA * 16;
                uint32_t ah[4];
                ldsm4(ah, addr);
#pragma unroll
                for (int nt = 0; nt < 4; nt++)
                    mma16816(acc[mt][nt], ah, bf[nt]);
            }
        }
    };

    if (AMODE == 2) {
        // ---- 4-stage cp.async pipeline (copy-only fp16 A/B) ----
        auto issue = [&](int c) {
            const int s = c & 3;
            const int k0 = c << 5;
            const __half* Ah = (const __half*)A;
            int kk = k0;
            if (A2 != nullptr && k0 >= 256) { Ah = (const __half*)A2; kk = k0 - 256; }
            const uint32_t stb = sb + s * PSTAGE;
#pragma unroll
            for (int i = 0; i < 2; i++) {
                int idx = i * 256 + tid;
                int r = idx >> 2, ch = idx & 3;
                int row = bm + r;
                int rc = row < M ? row : M - 1;
                int sz = row < M ? 16 : 0;
                CP_ASYNC16(stb + r * ROWB + ch * 16,
                           Ah + (size_t)rc * lda + kk + ch * 8, sz);
            }
#pragma unroll
            for (int i = 0; i < 2; i++) {
                int idx = i * 256 + tid;
                int r = idx >> 2, ch = idx & 3;
                CP_ASYNC16(stb + BUF + r * ROWB + ch * 16,
                           Bt + (size_t)(bn + r) * Ktot + k0 + ch * 8, 16);
            }
            CP_COMMIT();
        };

        int issued = 0;
        for (; issued < 3 && issued < nch; issued++) issue(issued);
        for (int c = 0; c < nch; c++) {
            CP_WAIT2();
            __syncthreads();
            if (issued < nch) { issue(issued); issued++; }
            mmaS(sb + (c & 3) * PSTAGE, BUF);
            __syncthreads();
        }
    } else {
        // ---- AMODE 1: reg-staged double buffer with fp16 convert ----
        float4 aReg[4];
        uint4 bReg[2];
        auto loadG = [&](int c) {
            const int k0 = c << 5;
            const float* Af = (const float*)A;
#pragma unroll
            for (int i = 0; i < 4; i++) {
                int idx = i * 256 + tid;
                int r = idx >> 3, c4 = idx & 7;
                int row = bm + r;
                aReg[i] = (row < M)
                    ? __ldg((const float4*)(Af + (size_t)row * lda + k0) + c4)
                    : make_float4(0.f, 0.f, 0.f, 0.f);
            }
#pragma unroll
            for (int i = 0; i < 2; i++) {
                int idx = i * 256 + tid;
                int r = idx >> 2, ch = idx & 3;
                bReg[i] = __ldg((const uint4*)(Bt + (size_t)(bn + r) * Ktot + k0 + ch * 8));
            }
        };
        auto storeS = [&](int s) {
            char* st = smem + s * STAGE1;
#pragma unroll
            for (int i = 0; i < 4; i++) {
                int idx = i * 256 + tid;
                int r = idx >> 3, c4 = idx & 7;
                float4 v = aReg[i];
                uint2 ph;
                ph.x = pack2h(__float2half(v.x), __float2half(v.y));
                ph.y = pack2h(__float2half(v.z), __float2half(v.w));
                *(uint2*)(st + r * ROWB + c4 * 8) = ph;
            }
#pragma unroll
            for (int i = 0; i < 2; i++) {
                int idx = i * 256 + tid;
                int r = idx >> 2, ch = idx & 3;
                *(uint4*)(st + 2 * BUF + r * ROWB + ch * 16) = bReg[i];
            }
        };

        loadG(0);
        storeS(0);
        __syncthreads();
        for (int c = 0; c < nch; c++) {
            if (c + 1 < nch) loadG(c + 1);
            mmaS(sb + (c & 1) * STAGE1, 2 * BUF);
            if (c + 1 < nch) storeS((c + 1) & 1);
            __syncthreads();
        }
    }

    // Epilogue
#pragma unroll
    for (int mt = 0; mt < 4; mt++) {
        int row0 = bm + warpM * 64 + mt * 16 + (lane >> 2);
#pragma unroll
        for (int nt = 0; nt < 4; nt++) {
            int col = bn + warpN * 32 + nt * 8 + (lane & 3) * 2;
            float bx2 = 0.f, by2 = 0.f;
            if (BIAS) { bx2 = __ldg(bias + col); by2 = __ldg(bias + col + 1); }
            float2 v0 = make_float2(acc[mt][nt][0] + bx2, acc[mt][nt][1] + by2);
            float2 v1 = make_float2(acc[mt][nt][2] + bx2, acc[mt][nt][3] + by2);
            if (RELU) {
                v0.x = fmaxf(v0.x, 0.f); v0.y = fmaxf(v0.y, 0.f);
                v1.x = fmaxf(v1.x, 0.f); v1.y = fmaxf(v1.y, 0.f);
            }
            if (OUTH) {
                __half* Ch = (__half*)C;
                if (row0 < M)
                    *(uint32_t*)(Ch + (size_t)row0 * 256 + col) =
                        pack2h(__float2half(v0.x), __float2half(v0.y));
                if (row0 + 8 < M)
                    *(uint32_t*)(Ch + (size_t)(row0 + 8) * 256 + col) =
                        pack2h(__float2half(v1.x), __float2half(v1.y));
            } else {
                float* Cf = (float*)C;
                if (row0 < M)     *(float2*)(Cf + (size_t)row0 * 256 + col) = v0;
                if (row0 + 8 < M) *(float2*)(Cf + (size_t)(row0 + 8) * 256 + col) = v1;
            }
        }
    }
}

// ---------------------------------------------------------------------------
extern "C" void kernel_launch(void* const* d_in, const int* in_sizes, int n_in,
                              void* d_out, int out_size)
{
    const float* x_t  = (const float*)d_in[0];
    const float* xs0  = (const float*)d_in[1];
    const float* xs1  = (const float*)d_in[2];
    const float* v0   = (const float*)d_in[3];
    const float* v1   = (const float*)d_in[4];
    const int*   r0   = (const int*)d_in[5];
    const int*   c0   = (const int*)d_in[6];
    const int*   r1   = (const int*)d_in[7];
    const int*   c1   = (const int*)d_in[8];
    const float* W0   = (const float*)d_in[9];
    const float* W1   = (const float*)d_in[10];
    const float* mW0  = (const float*)d_in[11];
    const float* mb0  = (const float*)d_in[12];
    const float* mW1  = (const float*)d_in[13];
    const float* mb1  = (const float*)d_in[14];
    const float* Wm   = (const float*)d_in[15];
    const float* bmv  = (const float*)d_in[16];
    float* out = (float*)d_out;

    float *sup0f, *sup1f, *a0, *b0, *a1, *b1;
    __half *wt0, *wt1, *mwt0, *mwt1, *wmt;
    int *cnt, *off, *bsum, *ecol;
    float *eval;
    cudaGetSymbolAddress((void**)&sup0f, g_sup0);
    cudaGetSymbolAddress((void**)&sup1f, g_sup1);
    cudaGetSymbolAddress((void**)&a0, g_a0);
    cudaGetSymbolAddress((void**)&b0, g_b0);
    cudaGetSymbolAddress((void**)&a1, g_a1);
    cudaGetSymbolAddress((void**)&b1, g_b1);
    cudaGetSymbolAddress((void**)&wt0, g_wt0);
    cudaGetSymbolAddress((void**)&wt1, g_wt1);
    cudaGetSymbolAddress((void**)&mwt0, g_mwt0);
    cudaGetSymbolAddress((void**)&mwt1, g_mwt1);
    cudaGetSymbolAddress((void**)&wmt, g_wmt);
    cudaGetSymbolAddress((void**)&cnt, g_cnt);
    cudaGetSymbolAddress((void**)&off, g_off);
    cudaGetSymbolAddress((void**)&bsum, g_bsum);
    cudaGetSymbolAddress((void**)&ecol, g_ecol);
    cudaGetSymbolAddress((void**)&eval, g_eval);

    __half* sup0 = (__half*)sup0f;
    __half* sup1 = (__half*)sup1f;
    __half* agg0 = (__half*)a0;   // fp16 agg (L1 input)
    __half* agg1 = (__half*)a1;
    __half* h0 = (__half*)b0;     // fp16 L1/L3 outputs
    __half* h1 = (__half*)b1;
    __half* q0 = (__half*)a0;     // fp16 L2 outputs (agg dead after L1)
    __half* q1 = (__half*)a1;

    cudaFuncSetAttribute(mma_gemm<1, true, false, false>,
                         cudaFuncAttributeMaxDynamicSharedMemorySize, SMEMT);
    cudaFuncSetAttribute(mma_gemm<2, true, true, true>,
                         cudaFuncAttributeMaxDynamicSharedMemorySize, SMEMT);
    cudaFuncSetAttribute(mma_gemm<2, false, true, false>,
                         cudaFuncAttributeMaxDynamicSharedMemorySize, SMEMT);

    // ---- Weight prep ----
    dim3 gp1((128 * 256 + 255) / 256, 1);
    prep_w<<<gp1, 256>>>(W0, wt0, 128);
    prep_w<<<gp1, 256>>>(W1, wt1, 128);
    dim3 gp3((256 * 256 + 255) / 256, 3);
    prep_w<<<gp3, 256>>>(mW0, mwt0, 256);
    prep_w<<<gp3, 256>>>(mW1, mwt1, 256);
    dim3 gpm((512 * 256 + 255) / 256, 1);
    prep_w<<<gpm, 256>>>(Wm, wmt, 512);

    // ---- CSR build ----
    const int nblk = (NROWS + 255) / 256;   // 391
    cudaMemsetAsync(cnt, 0, NROWS * sizeof(int));
    k_hist<<<(2 * NE + 255) / 256, 256>>>(r0, r1, cnt);
    k_bsum<<<nblk, 256>>>(cnt, bsum);
    k_bscan<<<1, 512>>>(bsum, nblk);
    k_off<<<nblk, 256>>>(cnt, bsum, off);
    cudaMemsetAsync(cnt, 0, NROWS * sizeof(int));
    k_fill<<<(2 * NE + 255) / 256, 256>>>(r0, r1, c0, c1, v0, v1,
                                          off, cnt, ecol, eval);

    dim3 blk(256);
    const int xS = (NS + 127) / 128;   // 782
    const int xT = (NT + 127) / 128;   // 391
    dim3 gS(2 * xS, 2);
    dim3 gT(2 * xT, 2);
    dim3 gM(xT, 2);

    // support = fp16(x_src) @ W  (1 MMA, fp16 out, both branches)
    mma_gemm<1, true, false, false><<<gS, blk, SMEMT>>>(
        xs0, xs1, nullptr, nullptr, wt0, wt1, nullptr, nullptr,
        sup0, sup1, NS, 128, 128, xS);

    // CSR aggregate: agg = fp16(x_t + A @ sup)   (no atomics)
    k_agg<<<(NROWS + 7) / 8, 256>>>(x_t, sup0, sup1, off, ecol, eval,
                                    agg0, agg1);

    // MLP L1: fp16 agg -> fp16 h  (cp.async pipeline)
    mma_gemm<2, true, true, true><<<gT, blk, SMEMT>>>(
        agg0, agg1, nullptr, nullptr, mwt0, mwt1, mb0, mb1,
        h0, h1, NT, 256, 256, xT);
    // MLP L2: fp16 h -> fp16 q
    mma_gemm<2, true, true, true><<<gT, blk, SMEMT>>>(
        h0, h1, nullptr, nullptr, mwt0 + 65536, mwt1 + 65536,
        mb0 + 256, mb1 + 256, q0, q1, NT, 256, 256, xT);
    // MLP L3: fp16 q -> fp16 h
    mma_gemm<2, true, true, true><<<gT, blk, SMEMT>>>(
        q0, q1, nullptr, nullptr, mwt0 + 2 * 65536, mwt1 + 2 * 65536,
        mb0 + 512, mb1 + 512, h0, h1, NT, 256, 256, xT);

    // merge: out = [h0, h1] @ Wm + bm  (fp16 A, K=512)
    mma_gemm<2, false, true, false><<<gM, blk, SMEMT>>>(
        h0, nullptr, h1, nullptr, wmt, nullptr, bmv, nullptr,
        out, nullptr, NT, 512, 256, xT);
}

// round 17
// speedup vs baseline: 2.7012x; 1.0830x over previous
#include <cuda_runtime.h>
#include <cuda_fp16.h>
#include <cstdint>

// Problem constants
#define NT 50000
#define NS 100000
#define NE 400000
#define CIN 128
#define CCH 256
#define NROWS (2 * NT)            /* both branches concatenated */

// ---------------------------------------------------------------------------
// Scratch (device globals — no allocation allowed)
// ---------------------------------------------------------------------------
__device__ float g_sup0[(size_t)NS * CCH];   // aliased fp16 support
__device__ float g_sup1[(size_t)NS * CCH];
__device__ float g_a0[(size_t)NT * CCH];     // fp16 agg, then fp16 L2 out
__device__ float g_b0[(size_t)NT * CCH];     // fp16 L1/L3 out
__device__ float g_a1[(size_t)NT * CCH];
__device__ float g_b1[(size_t)NT * CCH];
// fp16 transposed weights: [N=256, K] K-major
__device__ __half g_wt0[256 * 128];
__device__ __half g_wt1[256 * 128];
__device__ __half g_mwt0[3 * 256 * 256];
__device__ __half g_mwt1[3 * 256 * 256];
__device__ __half g_wmt[256 * 512];
// CSR scratch
__device__ int   g_cnt[NROWS];
__device__ int   g_off[NROWS + 1];
__device__ int   g_bsum[512];
__device__ int   g_ecol[2 * NE];
__device__ float g_eval[2 * NE];

// ---------------------------------------------------------------------------
// Helpers
// ---------------------------------------------------------------------------
__device__ __forceinline__ uint32_t smem_u32(const void* p) {
    uint32_t a;
    asm("{ .reg .u64 t; cvta.to.shared.u64 t, %1; cvt.u32.u64 %0, t; }"
        : "=r"(a) : "l"(p));
    return a;
}

__device__ __forceinline__ void ldsm4(uint32_t* r, uint32_t addr) {
    asm volatile("ldmatrix.sync.aligned.m8n8.x4.shared.b16 {%0,%1,%2,%3}, [%4];"
                 : "=r"(r[0]), "=r"(r[1]), "=r"(r[2]), "=r"(r[3]) : "r"(addr));
}

__device__ __forceinline__ void mma16816(float* d, const uint32_t* a, const uint32_t* b) {
    asm volatile(
        "mma.sync.aligned.m16n8k16.row.col.f32.f16.f16.f32 "
        "{%0,%1,%2,%3}, {%4,%5,%6,%7}, {%8,%9}, {%0,%1,%2,%3};"
        : "+f"(d[0]), "+f"(d[1]), "+f"(d[2]), "+f"(d[3])
        : "r"(a[0]), "r"(a[1]), "r"(a[2]), "r"(a[3]), "r"(b[0]), "r"(b[1]));
}

__device__ __forceinline__ uint32_t pack2h(__half x, __half y) {
    return ((uint32_t)__half_as_ushort(y) << 16) | __half_as_ushort(x);
}

#define CP_ASYNC16(dst, src, sz) \
    asm volatile("cp.async.cg.shared.global [%0], [%1], 16, %2;" \
                 :: "r"(dst), "l"(src), "r"(sz) : "memory")
#define CP_COMMIT() asm volatile("cp.async.commit_group;" ::: "memory")
#define CP_WAIT1()  asm volatile("cp.async.wait_group 1;" ::: "memory")
#define CP_WAIT0()  asm volatile("cp.async.wait_group 0;" ::: "memory")

// ---------------------------------------------------------------------------
// Fused weight prep: all 10 matrices W[K,256] fp32 -> Wt[256,K] fp16,
// 32x32 smem-tile transpose, coalesced loads and stores. 576 blocks total.
// ---------------------------------------------------------------------------
__global__ __launch_bounds__(256) void prep_all(
    const float* __restrict__ W0, const float* __restrict__ W1,
    const float* __restrict__ mW0, const float* __restrict__ mW1,
    const float* __restrict__ Wm,
    __half* __restrict__ wt0, __half* __restrict__ wt1,
    __half* __restrict__ mwt0, __half* __restrict__ mwt1,
    __half* __restrict__ wmt)
{
    int id = blockIdx.x;
    const float* src; __half* dst; int K;
    if (id < 32)       { src = W0; dst = wt0; K = 128; }
    else if (id < 64)  { src = W1; dst = wt1; K = 128; id -= 32; }
    else if (id < 448) {
        int l = (id - 64) >> 6; id = (id - 64) & 63; K = 256;
        if (l < 3) { src = mW0 + l * 65536;       dst = mwt0 + l * 65536; }
        else       { src = mW1 + (l - 3) * 65536; dst = mwt1 + (l - 3) * 65536; }
    } else             { id -= 448; src = Wm; dst = wmt; K = 512; }
    int kt = id >> 3, nt = id & 7;

    __shared__ __half sm[32][33];
    int tr = threadIdx.x >> 5, tc = threadIdx.x & 31;
#pragma unroll
    for (int i = 0; i < 4; i++) {
        int r = tr + i * 8;
        sm[r][tc] = __float2half(src[(size_t)(kt * 32 + r) * 256 + nt * 32 + tc]);
    }
    __syncthreads();
#pragma unroll
    for (int i = 0; i < 4; i++) {
        int n = tr + i * 8;
        dst[(size_t)(nt * 32 + n) * K + kt * 32 + tc] = sm[tc][n];
    }
}

// ---------------------------------------------------------------------------
// CSR build: histogram -> scan -> permuted fill
// ---------------------------------------------------------------------------
__global__ __launch_bounds__(256) void k_hist(
    const int* __restrict__ r0, const int* __restrict__ r1, int* __restrict__ cnt)
{
    int idx = blockIdx.x * 256 + threadIdx.x;
    if (idx >= 2 * NE) return;
    int g = (idx < NE) ? __ldg(r0 + idx) : (NT + __ldg(r1 + idx - NE));
    atomicAdd(cnt + g, 1);
}

__global__ __launch_bounds__(256) void k_bsum(
    const int* __restrict__ cnt, int* __restrict__ bsum)
{
    __shared__ int sm[256];
    int g = blockIdx.x * 256 + threadIdx.x;
    sm[threadIdx.x] = (g < NROWS) ? cnt[g] : 0;
    __syncthreads();
    for (int s = 128; s > 0; s >>= 1) {
        if (threadIdx.x < s) sm[threadIdx.x] += sm[threadIdx.x + s];
        __syncthreads();
    }
    if (threadIdx.x == 0) bsum[blockIdx.x] = sm[0];
}

__global__ __launch_bounds__(512) void k_bscan(int* __restrict__ bsum, int nblk)
{
    __shared__ int sm[512];
    int t = threadIdx.x;
    int own = (t < nblk) ? bsum[t] : 0;
    sm[t] = own;
    __syncthreads();
    for (int s = 1; s < 512; s <<= 1) {
        int add = (t >= s) ? sm[t - s] : 0;
        __syncthreads();
        sm[t] += add;
        __syncthreads();
    }
    if (t < nblk) bsum[t] = sm[t] - own;   // exclusive
}

// Also zeroes cnt after reading (so the follow-up fill can use it as cursor).
__global__ __launch_bounds__(256) void k_off(
    int* __restrict__ cnt, const int* __restrict__ bsum, int* __restrict__ off)
{
    __shared__ int sm[256];
    int g = blockIdx.x * 256 + threadIdx.x;
    int own = (g < NROWS) ? cnt[g] : 0;
    sm[threadIdx.x] = own;
    __syncthreads();
    for (int s = 1; s < 256; s <<= 1) {
        int add = (threadIdx.x >= (unsigned)s) ? sm[threadIdx.x - s] : 0;
        __syncthreads();
        sm[threadIdx.x] += add;
        __syncthreads();
    }
    if (g < NROWS) {
        off[g] = sm[threadIdx.x] - own + bsum[blockIdx.x];
        cnt[g] = 0;
    }
    if (g == 0) off[NROWS] = 2 * NE;
}

__global__ __launch_bounds__(256) void k_fill(
    const int* __restrict__ r0, const int* __restrict__ r1,
    const int* __restrict__ c0, const int* __restrict__ c1,
    const float* __restrict__ v0, const float* __restrict__ v1,
    const int* __restrict__ off, int* __restrict__ cur,
    int* __restrict__ ecol, float* __restrict__ eval)
{
    int idx = blockIdx.x * 256 + threadIdx.x;
    if (idx >= 2 * NE) return;
    int g, c; float v;
    if (idx < NE) {
        g = __ldg(r0 + idx); c = __ldg(c0 + idx); v = __ldg(v0 + idx);
    } else {
        int e = idx - NE;
        g = NT + __ldg(r1 + e); c = __ldg(c1 + e); v = __ldg(v1 + e);
    }
    int pos = __ldg(off + g) + atomicAdd(cur + g, 1);
    ecol[pos] = c;
    eval[pos] = v;
}

// ---------------------------------------------------------------------------
// CSR aggregate: one warp per target row. 8 ch/lane (uint4 fp16 gather).
// agg_fp16[row] = fp16( x_target[row] + sum_e val_e * sup[col_e] )
// ---------------------------------------------------------------------------
__global__ __launch_bounds__(256) void k_agg(
    const float* __restrict__ x_t,
    const __half* __restrict__ sup0, const __half* __restrict__ sup1,
    const int* __restrict__ off,
    const int* __restrict__ ecol, const float* __restrict__ eval,
    __half* __restrict__ agg0, __half* __restrict__ agg1)
{
    int t = blockIdx.x * 8 + (threadIdx.x >> 5);
    if (t >= NROWS) return;
    const int lane = threadIdx.x & 31;
    const bool br = (t >= NT);
    const int row = br ? t - NT : t;
    const __half* sup = br ? sup1 : sup0;
    __half* agg = br ? agg1 : agg0;

    float acc[8];
    {
        const float4* xp = (const float4*)(x_t + (size_t)row * CCH + lane * 8);
        float4 x0 = __ldg(xp), x1 = __ldg(xp + 1);
        acc[0] = x0.x; acc[1] = x0.y; acc[2] = x0.z; acc[3] = x0.w;
        acc[4] = x1.x; acc[5] = x1.y; acc[6] = x1.z; acc[7] = x1.w;
    }
    int i0 = __ldg(off + t), i1 = __ldg(off + t + 1);
    for (int i = i0; i < i1; i++) {
        int c = __ldg(ecol + i);
        float v = __ldg(eval + i);
        uint4 s = __ldg((const uint4*)(sup + (size_t)c * CCH + lane * 8));
        float2 f0 = __half22float2(*(const __half2*)&s.x);
        float2 f1 = __half22float2(*(const __half2*)&s.y);
        float2 f2 = __half22float2(*(const __half2*)&s.z);
        float2 f3 = __half22float2(*(const __half2*)&s.w);
        acc[0] = fmaf(v, f0.x, acc[0]); acc[1] = fmaf(v, f0.y, acc[1]);
        acc[2] = fmaf(v, f1.x, acc[2]); acc[3] = fmaf(v, f1.y, acc[3]);
        acc[4] = fmaf(v, f2.x, acc[4]); acc[5] = fmaf(v, f2.y, acc[5]);
        acc[6] = fmaf(v, f3.x, acc[6]); acc[7] = fmaf(v, f3.y, acc[7]);
    }
    uint4 o;
    o.x = pack2h(__float2half(acc[0]), __float2half(acc[1]));
    o.y = pack2h(__float2half(acc[2]), __float2half(acc[3]));
    o.z = pack2h(__float2half(acc[4]), __float2half(acc[5]));
    o.w = pack2h(__float2half(acc[6]), __float2half(acc[7]));
    *(uint4*)(agg + (size_t)row * CCH + lane * 8) = o;
}

// ---------------------------------------------------------------------------
// mma.sync GEMM.
// AMODE 1: fp32 A, fp16 round in regs (2-stage reg pipeline, BK=32).
// AMODE 2: fp16 A, 2-stage cp.async pipeline, BK=64.
//   RACE-SAFE wait schedule: issue chunk c+1 BEFORE the wait, then
//   wait_group 1 while more chunks remain and wait_group 0 on the final
//   iteration — guarantees group c has retired before its MMA reads.
// Bt pre-rounded fp16 [256, Ktot] K-major. Dual-branch via blockIdx.x.
// A2: second A source for k >= 256 (merge, Ktot=512). OUTH: fp16 C.
// ---------------------------------------------------------------------------
#define ROWB 80                    /* AMODE1: BK=32, 64B data + 16B pad  */
#define BUF  (128 * ROWB)          /* 10240 B                            */
#define STAGE1 (3 * BUF)           /* AMODE1 stage: A, (gap), B          */
#define ROWB2 144                  /* AMODE2: BK=64, 128B data + 16B pad */
#define BUF2 (128 * ROWB2)         /* 18432 B                            */
#define PSTAGE (2 * BUF2)          /* AMODE2 stage: A + B = 36864 B      */
#define SMEMT  (2 * PSTAGE)        /* 73728 B (covers both modes)        */

template <int AMODE, bool OUTH, bool BIAS, bool RELU>
__global__ __launch_bounds__(256, 2) void mma_gemm(
    const void* __restrict__ Aa, const void* __restrict__ Ab,
    const void* __restrict__ A2a, const void* __restrict__ A2b,
    const __half* __restrict__ Ba, const __half* __restrict__ Bb,
    const float* __restrict__ biasa, const float* __restrict__ biasb,
    void* __restrict__ Ca, void* __restrict__ Cb,
    int M, int Ktot, int lda, int xblocks)
{
    extern __shared__ char smem[];
    const uint32_t sb = smem_u32(smem);
    const int tid = threadIdx.x;
    const int wid = tid >> 5;
    const int lane = tid & 31;
    const int warpM = wid >> 2;
    const int warpN = wid & 3;
    int bx = blockIdx.x;
    const bool sec = (bx >= xblocks);
    if (sec) bx -= xblocks;
    const int bm = bx * 128;
    const int bn = blockIdx.y * 128;
    const void* A  = sec ? Ab  : Aa;
    const void* A2 = sec ? A2b : A2a;
    const __half* Bt = sec ? Bb : Ba;
    const float* bias = sec ? biasb : biasa;
    void* C = sec ? Cb : Ca;

    float acc[4][4][4];
#pragma unroll
    for (int i = 0; i < 4; i++)
#pragma unroll
        for (int j = 0; j < 4; j++)
#pragma unroll
            for (int q = 0; q < 4; q++) acc[i][j][q] = 0.0f;

    if (AMODE == 2) {
        // ---- BK=64, 2-stage cp.async pipeline (race-safe waits) ----
        const int nch = Ktot >> 6;
        auto issue = [&](int c) {
            const int s = c & 1;
            const int k0 = c << 6;
            const __half* Ah = (const __half*)A;
            int kk = k0;
            if (A2 != nullptr && k0 >= 256) { Ah = (const __half*)A2; kk = k0 - 256; }
            const uint32_t stb = sb + s * PSTAGE;
#pragma unroll
            for (int i = 0; i < 4; i++) {
                int idx = i * 256 + tid;
                int r = idx >> 3, ch = idx & 7;
                int row = bm + r;
                int rc = row < M ? row : M - 1;
                int sz = row < M ? 16 : 0;
                CP_ASYNC16(stb + r * ROWB2 + ch * 16,
                           Ah + (size_t)rc * lda + kk + ch * 8, sz);
            }
#pragma unroll
            for (int i = 0; i < 4; i++) {
                int idx = i * 256 + tid;
                int r = idx >> 3, ch = idx & 7;
                CP_ASYNC16(stb + BUF2 + r * ROWB2 + ch * 16,
                           Bt + (size_t)(bn + r) * Ktot + k0 + ch * 8, 16);
            }
            CP_COMMIT();
        };

        issue(0);
        for (int c = 0; c < nch; c++) {
            if (c + 1 < nch) { issue(c + 1); CP_WAIT1(); }
            else             { CP_WAIT0(); }
            __syncthreads();
            const uint32_t base = sb + (c & 1) * PSTAGE;
#pragma unroll
            for (int ks = 0; ks < 4; ks++) {
                uint32_t bf[4][2];
#pragma unroll
                for (int ntp = 0; ntp < 2; ntp++) {
                    int rB = warpN * 32 + ntp * 16 + ((lane >> 4) & 1) * 8 + (lane & 7);
                    int cB = ks * 2 + ((lane >> 3) & 1);
                    uint32_t addr = base + BUF2 + rB * ROWB2 + cB * 16;
                    uint32_t q[4];
                    ldsm4(q, addr);
                    bf[ntp * 2][0] = q[0]; bf[ntp * 2][1] = q[1];
                    bf[ntp * 2 + 1][0] = q[2]; bf[ntp * 2 + 1][1] = q[3];
                }
#pragma unroll
                for (int mt = 0; mt < 4; mt++) {
                    int rA = warpM * 64 + mt * 16 + (lane & 15);
                    int cA = ks * 2 + (lane >> 4);
                    uint32_t addr = base + rA * ROWB2 + cA * 16;
                    uint32_t ah[4];
                    ldsm4(ah, addr);
#pragma unroll
                    for (int nt = 0; nt < 4; nt++)
                        mma16816(acc[mt][nt], ah, bf[nt]);
                }
            }
            __syncthreads();
        }
    } else {
        // ---- AMODE 1: BK=32 reg-staged double buffer with fp16 convert ----
        const int nch = Ktot >> 5;
        float4 aReg[4];
        uint4 bReg[2];
        auto loadG = [&](int c) {
            const int k0 = c << 5;
            const float* Af = (const float*)A;
#pragma unroll
            for (int i = 0; i < 4; i++) {
                int idx = i * 256 + tid;
                int r = idx >> 3, c4 = idx & 7;
                int row = bm + r;
                aReg[i] = (row < M)
                    ? __ldg((const float4*)(Af + (size_t)row * lda + k0) + c4)
                    : make_float4(0.f, 0.f, 0.f, 0.f);
            }
#pragma unroll
            for (int i = 0; i < 2; i++) {
                int idx = i * 256 + tid;
                int r = idx >> 2, ch = idx & 3;
                bReg[i] = __ldg((const uint4*)(Bt + (size_t)(bn + r) * Ktot + k0 + ch * 8));
            }
        };
        auto storeS = [&](int s) {
            char* st = smem + s * STAGE1;
#pragma unroll
            for (int i = 0; i < 4; i++) {
                int idx = i * 256 + tid;
                int r = idx >> 3, c4 = idx & 7;
                float4 v = aReg[i];
                uint2 ph;
                ph.x = pack2h(__float2half(v.x), __float2half(v.y));
                ph.y = pack2h(__float2half(v.z), __float2half(v.w));
                *(uint2*)(st + r * ROWB + c4 * 8) = ph;
            }
#pragma unroll
            for (int i = 0; i < 2; i++) {
                int idx = i * 256 + tid;
                int r = idx >> 2, ch = idx & 3;
                *(uint4*)(st + 2 * BUF + r * ROWB + ch * 16) = bReg[i];
            }
        };
        auto mmaS = [&](uint32_t base) {
#pragma unroll
            for (int ks = 0; ks < 2; ks++) {
                uint32_t bf[4][2];
#pragma unroll
                for (int ntp = 0; ntp < 2; ntp++) {
                    int rB = warpN * 32 + ntp * 16 + ((lane >> 4) & 1) * 8 + (lane & 7);
                    int cB = ks * 2 + ((lane >> 3) & 1);
                    uint32_t addr = base + 2 * BUF + rB * ROWB + cB * 16;
                    uint32_t q[4];
                    ldsm4(q, addr);
                    bf[ntp * 2][0] = q[0]; bf[ntp * 2][1] = q[1];
                    bf[ntp * 2 + 1][0] = q[2]; bf[ntp * 2 + 1][1] = q[3];
                }
#pragma unroll
                for (int mt = 0; mt < 4; mt++) {
                    int rA = warpM * 64 + mt * 16 + (lane & 15);
                    int cA = ks * 2 + (lane >> 4);
                    uint32_t addr = base + rA * ROWB + cA * 16;
                    uint32_t ah[4];
                    ldsm4(ah, addr);
#pragma unroll
                    for (int nt = 0; nt < 4; nt++)
                        mma16816(acc[mt][nt], ah, bf[nt]);
                }
            }
        };

        loadG(0);
        storeS(0);
        __syncthreads();
        for (int c = 0; c < nch; c++) {
            if (c + 1 < nch) loadG(c + 1);
            mmaS(sb + (c & 1) * STAGE1);
            if (c + 1 < nch) storeS((c + 1) & 1);
            __syncthreads();
        }
    }

    // Epilogue
#pragma unroll
    for (int mt = 0; mt < 4; mt++) {
        int row0 = bm + warpM * 64 + mt * 16 + (lane >> 2);
#pragma unroll
        for (int nt = 0; nt < 4; nt++) {
            int col = bn + warpN * 32 + nt * 8 + (lane & 3) * 2;
            float bx2 = 0.f, by2 = 0.f;
            if (BIAS) { bx2 = __ldg(bias + col); by2 = __ldg(bias + col + 1); }
            float2 v0 = make_float2(acc[mt][nt][0] + bx2, acc[mt][nt][1] + by2);
            float2 v1 = make_float2(acc[mt][nt][2] + bx2, acc[mt][nt][3] + by2);
            if (RELU) {
                v0.x = fmaxf(v0.x, 0.f); v0.y = fmaxf(v0.y, 0.f);
                v1.x = fmaxf(v1.x, 0.f); v1.y = fmaxf(v1.y, 0.f);
            }
            if (OUTH) {
                __half* Ch = (__half*)C;
                if (row0 < M)
                    *(uint32_t*)(Ch + (size_t)row0 * 256 + col) =
                        pack2h(__float2half(v0.x), __float2half(v0.y));
                if (row0 + 8 < M)
                    *(uint32_t*)(Ch + (size_t)(row0 + 8) * 256 + col) =
                        pack2h(__float2half(v1.x), __float2half(v1.y));
            } else {
                float* Cf = (float*)C;
                if (row0 < M)     *(float2*)(Cf + (size_t)row0 * 256 + col) = v0;
                if (row0 + 8 < M) *(float2*)(Cf + (size_t)(row0 + 8) * 256 + col) = v1;
            }
        }
    }
}

// ---------------------------------------------------------------------------
extern "C" void kernel_launch(void* const* d_in, const int* in_sizes, int n_in,
                              void* d_out, int out_size)
{
    const float* x_t  = (const float*)d_in[0];
    const float* xs0  = (const float*)d_in[1];
    const float* xs1  = (const float*)d_in[2];
    const float* v0   = (const float*)d_in[3];
    const float* v1   = (const float*)d_in[4];
    const int*   r0   = (const int*)d_in[5];
    const int*   c0   = (const int*)d_in[6];
    const int*   r1   = (const int*)d_in[7];
    const int*   c1   = (const int*)d_in[8];
    const float* W0   = (const float*)d_in[9];
    const float* W1   = (const float*)d_in[10];
    const float* mW0  = (const float*)d_in[11];
    const float* mb0  = (const float*)d_in[12];
    const float* mW1  = (const float*)d_in[13];
    const float* mb1  = (const float*)d_in[14];
    const float* Wm   = (const float*)d_in[15];
    const float* bmv  = (const float*)d_in[16];
    float* out = (float*)d_out;

    float *sup0f, *sup1f, *a0, *b0, *a1, *b1;
    __half *wt0, *wt1, *mwt0, *mwt1, *wmt;
    int *cnt, *off, *bsum, *ecol;
    float *eval;
    cudaGetSymbolAddress((void**)&sup0f, g_sup0);
    cudaGetSymbolAddress((void**)&sup1f, g_sup1);
    cudaGetSymbolAddress((void**)&a0, g_a0);
    cudaGetSymbolAddress((void**)&b0, g_b0);
    cudaGetSymbolAddress((void**)&a1, g_a1);
    cudaGetSymbolAddress((void**)&b1, g_b1);
    cudaGetSymbolAddress((void**)&wt0, g_wt0);
    cudaGetSymbolAddress((void**)&wt1, g_wt1);
    cudaGetSymbolAddress((void**)&mwt0, g_mwt0);
    cudaGetSymbolAddress((void**)&mwt1, g_mwt1);
    cudaGetSymbolAddress((void**)&wmt, g_wmt);
    cudaGetSymbolAddress((void**)&cnt, g_cnt);
    cudaGetSymbolAddress((void**)&off, g_off);
    cudaGetSymbolAddress((void**)&bsum, g_bsum);
    cudaGetSymbolAddress((void**)&ecol, g_ecol);
    cudaGetSymbolAddress((void**)&eval, g_eval);

    __half* sup0 = (__half*)sup0f;
    __half* sup1 = (__half*)sup1f;
    __half* agg0 = (__half*)a0;   // fp16 agg (L1 input)
    __half* agg1 = (__half*)a1;
    __half* h0 = (__half*)b0;     // fp16 L1/L3 outputs
    __half* h1 = (__half*)b1;
    __half* q0 = (__half*)a0;     // fp16 L2 outputs (agg dead after L1)
    __half* q1 = (__half*)a1;

    cudaFuncSetAttribute(mma_gemm<1, true, false, false>,
                         cudaFuncAttributeMaxDynamicSharedMemorySize, SMEMT);
    cudaFuncSetAttribute(mma_gemm<2, true, true, true>,
                         cudaFuncAttributeMaxDynamicSharedMemorySize, SMEMT);
    cudaFuncSetAttribute(mma_gemm<2, false, true, false>,
                         cudaFuncAttributeMaxDynamicSharedMemorySize, SMEMT);

    // ---- Fused weight prep (1 launch, smem-tile transpose) ----
    prep_all<<<576, 256>>>(W0, W1, mW0, mW1, Wm, wt0, wt1, mwt0, mwt1, wmt);

    // ---- CSR build ----
    const int nblk = (NROWS + 255) / 256;   // 391
    cudaMemsetAsync(cnt, 0, NROWS * sizeof(int));
    k_hist<<<(2 * NE + 255) / 256, 256>>>(r0, r1, cnt);
    k_bsum<<<nblk, 256>>>(cnt, bsum);
    k_bscan<<<1, 512>>>(bsum, nblk);
    k_off<<<nblk, 256>>>(cnt, bsum, off);   // also zeroes cnt
    k_fill<<<(2 * NE + 255) / 256, 256>>>(r0, r1, c0, c1, v0, v1,
                                          off, cnt, ecol, eval);

    dim3 blk(256);
    const int xS = (NS + 127) / 128;   // 782
    const int xT = (NT + 127) / 128;   // 391
    dim3 gS(2 * xS, 2);
    dim3 gT(2 * xT, 2);
    dim3 gM(xT, 2);

    // support = fp16(x_src) @ W  (AMODE 1, fp16 out, both branches)
    mma_gemm<1, true, false, false><<<gS, blk, SMEMT>>>(
        xs0, xs1, nullptr, nullptr, wt0, wt1, nullptr, nullptr,
        sup0, sup1, NS, 128, 128, xS);

    // CSR aggregate: agg = fp16(x_t + A @ sup)   (no atomics)
    k_agg<<<(NROWS + 7) / 8, 256>>>(x_t, sup0, sup1, off, ecol, eval,
                                    agg0, agg1);

    // MLP L1: fp16 agg -> fp16 h  (BK=64 cp.async pipeline)
    mma_gemm<2, true, true, true><<<gT, blk, SMEMT>>>(
        agg0, agg1, nullptr, nullptr, mwt0, mwt1, mb0, mb1,
        h0, h1, NT, 256, 256, xT);
    // MLP L2: fp16 h -> fp16 q
    mma_gemm<2, true, true, true><<<gT, blk, SMEMT>>>(
        h0, h1, nullptr, nullptr, mwt0 + 65536, mwt1 + 65536,
        mb0 + 256, mb1 + 256, q0, q1, NT, 256, 256, xT);
    // MLP L3: fp16 q -> fp16 h
    mma_gemm<2, true, true, true><<<gT, blk, SMEMT>>>(
        q0, q1, nullptr, nullptr, mwt0 + 2 * 65536, mwt1 + 2 * 65536,
        mb0 + 512, mb1 + 512, h0, h1, NT, 256, 256, xT);

    // merge: out = [h0, h1] @ Wm + bm  (fp16 A, K=512)
    mma_gemm<2, false, true, false><<<gM, blk, SMEMT>>>(
        h0, nullptr, h1, nullptr, wmt, nullptr, bmv, nullptr,
        out, nullptr, NT, 512, 256, xT);
}